// round 7
// baseline (speedup 1.0000x reference)
#include <cuda_runtime.h>
#include <cuda_bf16.h>
#include <cstdint>
#include <math.h>

#define NTOK 768
#define DMODEL 256
#define NHEAD 8

// ---------------- scratch (device globals; no allocations allowed) ----------
__device__ __nv_bfloat16 g_feat_bf[NTOK * DMODEL];
__device__ __nv_bfloat16 g_inw_bf[768 * 256];
__device__ __nv_bfloat16 g_outw_bf[256 * 256];
__device__ __nv_bfloat16 g_w1a_bf[256 * 256];
__device__ __nv_bfloat16 g_w1b_bf[256 * 256];
__device__ unsigned short g_w1c_f8[256 * 128];     // e4m3x2 pairs [n][d/2]
__device__ __nv_bfloat16 g_w2_bf[128 * 256];
__device__ __nv_bfloat16 g_w3_bf[64 * 128];
__device__ __nv_bfloat16 g_w4_bf[32 * 64];
__device__ __nv_bfloat16 g_qkv_bf[NTOK * 768];
__device__ __nv_bfloat16 g_vT_bf[NHEAD * 32 * NTOK];
__device__ __nv_bfloat16 g_o_bf[NTOK * DMODEL];
__device__ __nv_bfloat16 g_att_bf[NTOK * DMODEL];
__device__ __nv_bfloat16 g_Bp_bf[NTOK * DMODEL];
__device__ float g_Ap[NTOK * DMODEL];

// ---------------- helpers ----------------------------------------------------
__device__ __forceinline__ void mma_bf16(float* c, unsigned a0, unsigned a1,
                                         unsigned a2, unsigned a3,
                                         unsigned b0, unsigned b1)
{
    asm volatile(
        "mma.sync.aligned.m16n8k16.row.col.f32.bf16.bf16.f32 "
        "{%0,%1,%2,%3}, {%4,%5,%6,%7}, {%8,%9}, {%0,%1,%2,%3};"
        : "+f"(c[0]), "+f"(c[1]), "+f"(c[2]), "+f"(c[3])
        : "r"(a0), "r"(a1), "r"(a2), "r"(a3), "r"(b0), "r"(b1));
}
__device__ __forceinline__ void mma_e4m3(float* c, unsigned a0, unsigned a1,
                                         unsigned a2, unsigned a3,
                                         unsigned b0, unsigned b1)
{
    asm volatile(
        "mma.sync.aligned.m16n8k32.row.col.f32.e4m3.e4m3.f32 "
        "{%0,%1,%2,%3}, {%4,%5,%6,%7}, {%8,%9}, {%0,%1,%2,%3};"
        : "+f"(c[0]), "+f"(c[1]), "+f"(c[2]), "+f"(c[3])
        : "r"(a0), "r"(a1), "r"(a2), "r"(a3), "r"(b0), "r"(b1));
}
__device__ __forceinline__ unsigned pack_bf16(float a, float b)
{
    __nv_bfloat162 h;
    h.x = __float2bfloat16_rn(a);
    h.y = __float2bfloat16_rn(b);
    return *reinterpret_cast<unsigned*>(&h);
}
__device__ __forceinline__ float2 unpack_bf16(unsigned u)
{
    __nv_bfloat162 h = *reinterpret_cast<__nv_bfloat162*>(&u);
    return make_float2(__bfloat162float(h.x), __bfloat162float(h.y));
}
__device__ __forceinline__ unsigned short cvt_e4m3x2(float lo, float hi)
{
    unsigned short r;
    asm("cvt.rn.satfinite.e4m3x2.f32 %0, %1, %2;" : "=h"(r) : "f"(hi), "f"(lo));
    return r;
}
__device__ __forceinline__ unsigned pack4_e4m3(float f0, float f1, float f2, float f3)
{
    unsigned lo = cvt_e4m3x2(f0, f1);
    unsigned hi = cvt_e4m3x2(f2, f3);
    return lo | (hi << 16);
}
__device__ __forceinline__ float fexp2(float x)
{
    float y;
    asm("ex2.approx.ftz.f32 %0, %1;" : "=f"(y) : "f"(x));
    return y;
}

// ---------------- conversions -------------------------------------------------
__global__ void convert_pre(const float* __restrict__ features,
                            const float* __restrict__ in_w,
                            const float* __restrict__ out_w,
                            const float* __restrict__ w1,
                            const float* __restrict__ w2,
                            const float* __restrict__ w3,
                            const float* __restrict__ w4)
{
    int t = blockIdx.x * 256 + threadIdx.x;
    if (t < 196608) {
        g_feat_bf[t] = __float2bfloat16_rn(features[t]);
        g_inw_bf[t]  = __float2bfloat16_rn(in_w[t]);
    }
    if (t < 65536) {
        int n = t >> 8, d = t & 255;
        g_outw_bf[t] = __float2bfloat16_rn(out_w[t]);
        g_w1a_bf[t]  = __float2bfloat16_rn(w1[n * 771 + d]);
        g_w1b_bf[t]  = __float2bfloat16_rn(w1[n * 771 + 256 + d]);
    }
    if (t < 32768) {
        int n = t >> 7, d = (t & 127) * 2;
        g_w1c_f8[t] = cvt_e4m3x2(w1[n * 771 + 512 + d], w1[n * 771 + 512 + d + 1]);
        g_w2_bf[t] = __float2bfloat16_rn(w2[t]);
    }
    if (t < 8192)  g_w3_bf[t] = __float2bfloat16_rn(w3[t]);
    if (t < 2048)  g_w4_bf[t] = __float2bfloat16_rn(w4[t]);
}

__global__ void build_vT()
{
    int row = blockIdx.x;
    for (int m = threadIdx.x; m < NTOK; m += 256)
        g_vT_bf[row * NTOK + m] = g_qkv_bf[m * 768 + 512 + row];
}

// ---------------- bf16 GEMM, K=256, tile 64x128, 128 threads -----------------
#define GEMM_SMEM_U32 ((64 + 128) * 132)
#define GEMM_SMEM_BYTES (GEMM_SMEM_U32 * 4)

__global__ __launch_bounds__(128, 1) void gemm_bf256(
    const uint4* __restrict__ A4, const uint4* __restrict__ B4,
    const float* __restrict__ bias,
    float* __restrict__ Cf, uint32_t* __restrict__ Cb, int N)
{
    extern __shared__ uint32_t sg[];
    uint32_t* As = sg;              // 64 x 132
    uint32_t* Bs = sg + 64 * 132;   // 128 x 132

    const int m0 = blockIdx.y * 64;
    const int n0 = blockIdx.x * 128;
    const int t  = threadIdx.x;
    const int w  = t >> 5;
    const int lane = t & 31;
    const int g   = lane >> 2;
    const int tig = lane & 3;
    const int r0i = w * 16 + g, r1i = r0i + 8;

    for (int idx = t; idx < 2048; idx += 128) {
        int r = idx >> 5, c4 = idx & 31;
        *(uint4*)&As[r * 132 + c4 * 4] = A4[(m0 + r) * 32 + c4];
    }
    for (int idx = t; idx < 4096; idx += 128) {
        int r = idx >> 5, c4 = idx & 31;
        *(uint4*)&Bs[r * 132 + c4 * 4] = B4[(n0 + r) * 32 + c4];
    }
    __syncthreads();

    float acc[16][4];
#pragma unroll
    for (int nt = 0; nt < 16; nt++)
#pragma unroll
        for (int q = 0; q < 4; q++) acc[nt][q] = 0.f;

#pragma unroll
    for (int q = 0; q < 16; q++) {
        uint32_t a0 = As[r0i * 132 + 8 * q + tig];
        uint32_t a1 = As[r1i * 132 + 8 * q + tig];
        uint32_t a2 = As[r0i * 132 + 8 * q + 4 + tig];
        uint32_t a3 = As[r1i * 132 + 8 * q + 4 + tig];
#pragma unroll
        for (int nt = 0; nt < 16; nt++) {
            int n = 8 * nt + g;
            uint32_t b0 = Bs[n * 132 + 8 * q + tig];
            uint32_t b1 = Bs[n * 132 + 8 * q + 4 + tig];
            mma_bf16(acc[nt], a0, a1, a2, a3, b0, b1);
        }
    }

    const int gm0 = m0 + r0i, gm1 = m0 + r1i;
#pragma unroll
    for (int nt = 0; nt < 16; nt++) {
        int gn = n0 + 8 * nt + 2 * tig;
        float bi0 = bias ? bias[gn] : 0.f;
        float bi1 = bias ? bias[gn + 1] : 0.f;
        float v00 = acc[nt][0] + bi0, v01 = acc[nt][1] + bi1;
        float v10 = acc[nt][2] + bi0, v11 = acc[nt][3] + bi1;
        if (Cf) {
            *(float2*)&Cf[(size_t)gm0 * N + gn] = make_float2(v00, v01);
            *(float2*)&Cf[(size_t)gm1 * N + gn] = make_float2(v10, v11);
        }
        if (Cb) {
            Cb[gm0 * (N >> 1) + (gn >> 1)] = pack_bf16(v00, v01);
            Cb[gm1 * (N >> 1) + (gn >> 1)] = pack_bf16(v10, v11);
        }
    }
}

// ---------------- flash attention, 64-row q tiles, 128 threads ---------------
__global__ __launch_bounds__(128, 1) void attn_flash(float* /*unused*/)
{
    __shared__ uint32_t Ks[128 * 20];
    __shared__ uint32_t VTs[32 * 68];

    const int q0 = blockIdx.x * 64;
    const int h  = blockIdx.y;
    const int t  = threadIdx.x;
    const int w  = t >> 5;
    const int lane = t & 31;
    const int g   = lane >> 2;
    const int tig = lane & 3;
    const int r0i = w * 16 + g, r1i = r0i + 8;

    const uint32_t* qkvU = (const uint32_t*)g_qkv_bf;
    const uint32_t* vtU  = (const uint32_t*)g_vT_bf;

    const float CS = 1.4426950408889634f * 0.17677669529663687f;

    uint32_t qf[8];
#pragma unroll
    for (int qq = 0; qq < 2; qq++) {
        qf[4 * qq]     = qkvU[(q0 + r0i) * 384 + h * 16 + 8 * qq + tig];
        qf[4 * qq + 1] = qkvU[(q0 + r1i) * 384 + h * 16 + 8 * qq + tig];
        qf[4 * qq + 2] = qkvU[(q0 + r0i) * 384 + h * 16 + 8 * qq + 4 + tig];
        qf[4 * qq + 3] = qkvU[(q0 + r1i) * 384 + h * 16 + 8 * qq + 4 + tig];
    }

    float acc_o[4][4];
#pragma unroll
    for (int nt = 0; nt < 4; nt++)
#pragma unroll
        for (int e = 0; e < 4; e++) acc_o[nt][e] = 0.f;
    float m0s = -1e30f, m1s = -1e30f, l0p = 0.f, l1p = 0.f;

    for (int kt = 0; kt < 6; kt++) {
        __syncthreads();
        for (int idx = t; idx < 2048; idx += 128) {
            int r = idx >> 4, c = idx & 15;
            Ks[r * 20 + c] = qkvU[(kt * 128 + r) * 384 + 128 + h * 16 + c];
        }
        for (int idx = t; idx < 2048; idx += 128) {
            int d = idx >> 6, c = idx & 63;
            VTs[d * 68 + c] = vtU[(h * 32 + d) * 384 + kt * 64 + c];
        }
        __syncthreads();

        float accs[16][4];
#pragma unroll
        for (int nt = 0; nt < 16; nt++)
#pragma unroll
            for (int e = 0; e < 4; e++) accs[nt][e] = 0.f;
#pragma unroll
        for (int qq = 0; qq < 2; qq++) {
            uint32_t a0 = qf[4 * qq], a1 = qf[4 * qq + 1];
            uint32_t a2 = qf[4 * qq + 2], a3 = qf[4 * qq + 3];
#pragma unroll
            for (int nt = 0; nt < 16; nt++) {
                int n = 8 * nt + g;
                uint32_t b0 = Ks[n * 20 + 8 * qq + tig];
                uint32_t b1 = Ks[n * 20 + 8 * qq + 4 + tig];
                mma_bf16(accs[nt], a0, a1, a2, a3, b0, b1);
            }
        }
        float lm0 = -1e30f, lm1 = -1e30f;
#pragma unroll
        for (int nt = 0; nt < 16; nt++) {
            accs[nt][0] *= CS; accs[nt][1] *= CS;
            accs[nt][2] *= CS; accs[nt][3] *= CS;
            lm0 = fmaxf(lm0, fmaxf(accs[nt][0], accs[nt][1]));
            lm1 = fmaxf(lm1, fmaxf(accs[nt][2], accs[nt][3]));
        }
#pragma unroll
        for (int o = 1; o <= 2; o <<= 1) {
            lm0 = fmaxf(lm0, __shfl_xor_sync(0xffffffffu, lm0, o));
            lm1 = fmaxf(lm1, __shfl_xor_sync(0xffffffffu, lm1, o));
        }
        float mn0 = fmaxf(m0s, lm0), mn1 = fmaxf(m1s, lm1);
        float al0 = fexp2(m0s - mn0), al1 = fexp2(m1s - mn1);
        m0s = mn0; m1s = mn1;

        float ps0 = 0.f, ps1 = 0.f;
        uint32_t Pf[32];
#pragma unroll
        for (int nt = 0; nt < 16; nt++) {
            float p00 = fexp2(accs[nt][0] - mn0);
            float p01 = fexp2(accs[nt][1] - mn0);
            float p10 = fexp2(accs[nt][2] - mn1);
            float p11 = fexp2(accs[nt][3] - mn1);
            ps0 += p00 + p01; ps1 += p10 + p11;
            int q2 = nt >> 1, off = (nt & 1) * 2;
            Pf[4 * q2 + off]     = pack_bf16(p00, p01);
            Pf[4 * q2 + off + 1] = pack_bf16(p10, p11);
        }
        l0p = l0p * al0 + ps0;
        l1p = l1p * al1 + ps1;
#pragma unroll
        for (int nt = 0; nt < 4; nt++) {
            acc_o[nt][0] *= al0; acc_o[nt][1] *= al0;
            acc_o[nt][2] *= al1; acc_o[nt][3] *= al1;
        }
#pragma unroll
        for (int q = 0; q < 8; q++) {
            uint32_t a0 = Pf[4 * q], a1 = Pf[4 * q + 1];
            uint32_t a2 = Pf[4 * q + 2], a3 = Pf[4 * q + 3];
#pragma unroll
            for (int nt = 0; nt < 4; nt++) {
                int n = 8 * nt + g;
                uint32_t b0 = VTs[n * 68 + 8 * q + tig];
                uint32_t b1 = VTs[n * 68 + 8 * q + 4 + tig];
                mma_bf16(acc_o[nt], a0, a1, a2, a3, b0, b1);
            }
        }
    }

#pragma unroll
    for (int o = 1; o <= 2; o <<= 1) {
        l0p += __shfl_xor_sync(0xffffffffu, l0p, o);
        l1p += __shfl_xor_sync(0xffffffffu, l1p, o);
    }
    float inv0 = 1.f / l0p, inv1 = 1.f / l1p;
    uint32_t* oU = (uint32_t*)g_o_bf;
#pragma unroll
    for (int nt = 0; nt < 4; nt++) {
        oU[(q0 + r0i) * 128 + h * 16 + 4 * nt + tig] =
            pack_bf16(acc_o[nt][0] * inv0, acc_o[nt][1] * inv0);
        oU[(q0 + r1i) * 128 + h * 16 + 4 * nt + tig] =
            pack_bf16(acc_o[nt][2] * inv1, acc_o[nt][3] * inv1);
    }
}

// ---------------- fused all-pairs MLP: fp8 L1 + bf16 L2-L4 -------------------
// SMEM u32 offsets (all bases ≡ 0 mod 32)
#define OFF_W1   0            // fp8: 256 x 68 (64 data u32/row)
#define OFF_W2   17408        // bf16: 128 x 132
#define OFF_W3   34304        // bf16: 64 x 68
#define OFF_W4   38656        // bf16: 32 x 36
#define OFF_PACK 39808        // float4[256]
#define OFF_LGB  40832        // float2[256]
#define OFF_B2   41344
#define OFF_B3   41472
#define OFF_B4   41536
#define OFF_W5   41568
#define OFF_B5   41600
#define SMEM_U32 41604
#define SMEM_BYTES (SMEM_U32 * 4)

__global__ __launch_bounds__(256, 1) void fused_pairs_reg(
    const float* __restrict__ boxes,
    const float* __restrict__ w1,
    const float* __restrict__ Ap,
    const uint32_t* __restrict__ attbf,
    const uint32_t* __restrict__ bpbf,
    const uint4* __restrict__ w1f8v, const uint4* __restrict__ w2v,
    const uint4* __restrict__ w3v, const uint4* __restrict__ w4v,
    const float* __restrict__ lng, const float* __restrict__ lnb,
    const float* __restrict__ b2, const float* __restrict__ b3,
    const float* __restrict__ b4,
    const float* __restrict__ w5, const float* __restrict__ b5,
    float* __restrict__ out)
{
    extern __shared__ uint32_t sm[];
    uint32_t* W1s = sm + OFF_W1;
    uint32_t* W2s = sm + OFF_W2;
    uint32_t* W3s = sm + OFF_W3;
    uint32_t* W4s = sm + OFF_W4;
    float4*   sPack = (float4*)(sm + OFF_PACK);
    float2*   sLgb  = (float2*)(sm + OFF_LGB);
    float*    sB2   = (float*)(sm + OFF_B2);
    float*    sB3   = (float*)(sm + OFF_B3);
    float*    sB4   = (float*)(sm + OFF_B4);
    float*    sW5   = (float*)(sm + OFF_W5);
    float*    sB5   = (float*)(sm + OFF_B5);

    const int i  = blockIdx.y;
    const int j0 = blockIdx.x * 128;
    const int t  = threadIdx.x;
    const int w  = t >> 5;
    const int lane = t & 31;
    const int g   = lane >> 2;
    const int tig = lane & 3;

    // ---- stage weights + consts
    for (int idx = t; idx < 4096; idx += 256) {        // w1c fp8: 256 rows x 16 uint4
        int r = idx >> 4, c4 = idx & 15;
        *(uint4*)&W1s[r * 68 + c4 * 4] = w1f8v[idx];
    }
    for (int idx = t; idx < 4096; idx += 256) {        // w2 bf16: 128 x 32 uint4
        int r = idx >> 5, c4 = idx & 31;
        *(uint4*)&W2s[r * 132 + c4 * 4] = w2v[idx];
    }
    for (int idx = t; idx < 1024; idx += 256) {
        int r = idx >> 4, c4 = idx & 15;
        *(uint4*)&W3s[r * 68 + c4 * 4] = w3v[idx];
    }
    for (int idx = t; idx < 256; idx += 256) {
        int r = idx >> 3, c4 = idx & 7;
        *(uint4*)&W4s[r * 36 + c4 * 4] = w4v[idx];
    }
    {
        int k = t;
        sPack[k] = make_float4(Ap[i * 256 + k], w1[k * 771 + 768],
                               w1[k * 771 + 769], w1[k * 771 + 770]);
        sLgb[k]  = make_float2(lng[k], lnb[k]);
        if (k < 128) sB2[k] = b2[k];
        if (k < 64)  sB3[k] = b3[k];
        if (k < 32)  { sB4[k] = b4[k]; sW5[k] = w5[k]; }
        if (k == 0)  sB5[0] = b5[0];
    }
    __syncthreads();

    const int r0 = w * 16 + g, r1 = r0 + 8;
    const int jr0 = j0 + r0, jr1 = j0 + r1;

    float bxi = boxes[i * 4], byi = boxes[i * 4 + 1];
    float dy0 = byi - boxes[jr0 * 4 + 1];
    float dy1 = byi - boxes[jr1 * 4 + 1];
    float sx0 = fabsf(bxi - boxes[jr0 * 4]), sya0 = fabsf(dy0), sys0 = dy0;
    float sx1 = fabsf(bxi - boxes[jr1 * 4]), sya1 = fabsf(dy1), sys1 = dy1;

    // ---- build fp8 A fragments: per k-group of 32, a0/a1 = k[4tig..4tig+3]
    // rows jr0/jr1, a2/a3 = same +16.
    uint32_t A18[32];
#pragma unroll
    for (int q8 = 0; q8 < 8; q8++) {
        int uL = 16 * q8 + 2 * tig;      // low-k u32 idx (covers d=4tig..4tig+3)
        int uH = uL + 8;                  // high-k (+16 bytes)
        float2 aiL0 = unpack_bf16(attbf[i * 128 + uL]);
        float2 aiL1 = unpack_bf16(attbf[i * 128 + uL + 1]);
        float2 aiH0 = unpack_bf16(attbf[i * 128 + uH]);
        float2 aiH1 = unpack_bf16(attbf[i * 128 + uH + 1]);
        float2 j0L0 = unpack_bf16(attbf[jr0 * 128 + uL]);
        float2 j0L1 = unpack_bf16(attbf[jr0 * 128 + uL + 1]);
        float2 j0H0 = unpack_bf16(attbf[jr0 * 128 + uH]);
        float2 j0H1 = unpack_bf16(attbf[jr0 * 128 + uH + 1]);
        float2 j1L0 = unpack_bf16(attbf[jr1 * 128 + uL]);
        float2 j1L1 = unpack_bf16(attbf[jr1 * 128 + uL + 1]);
        float2 j1H0 = unpack_bf16(attbf[jr1 * 128 + uH]);
        float2 j1H1 = unpack_bf16(attbf[jr1 * 128 + uH + 1]);
        A18[4 * q8]     = pack4_e4m3(j0L0.x * aiL0.x, j0L0.y * aiL0.y,
                                     j0L1.x * aiL1.x, j0L1.y * aiL1.y);
        A18[4 * q8 + 1] = pack4_e4m3(j1L0.x * aiL0.x, j1L0.y * aiL0.y,
                                     j1L1.x * aiL1.x, j1L1.y * aiL1.y);
        A18[4 * q8 + 2] = pack4_e4m3(j0H0.x * aiH0.x, j0H0.y * aiH0.y,
                                     j0H1.x * aiH1.x, j0H1.y * aiH1.y);
        A18[4 * q8 + 3] = pack4_e4m3(j1H0.x * aiH0.x, j1H0.y * aiH0.y,
                                     j1H1.x * aiH1.x, j1H1.y * aiH1.y);
    }

    // ================= layer 1 (fp8): N=256, K=256 ===========================
    uint32_t H1[64];
    float sum0 = 0.f, sq0 = 0.f, sum1 = 0.f, sq1 = 0.f;
#pragma unroll
    for (int h = 0; h < 2; h++) {
        float acc[16][4];
#pragma unroll
        for (int ntl = 0; ntl < 16; ntl++)
#pragma unroll
            for (int q = 0; q < 4; q++) acc[ntl][q] = 0.f;

#pragma unroll
        for (int q8 = 0; q8 < 8; q8++) {
            uint32_t a0 = A18[4 * q8],     a1 = A18[4 * q8 + 1];
            uint32_t a2 = A18[4 * q8 + 2], a3 = A18[4 * q8 + 3];
#pragma unroll
            for (int ntl = 0; ntl < 16; ntl++) {
                int n = (h * 16 + ntl) * 8 + g;
                uint32_t b0 = W1s[n * 68 + 8 * q8 + tig];
                uint32_t b1 = W1s[n * 68 + 8 * q8 + 4 + tig];
                mma_e4m3(acc[ntl], a0, a1, a2, a3, b0, b1);
            }
        }
#pragma unroll
        for (int ntl = 0; ntl < 16; ntl++) {
            int nt = h * 16 + ntl;
            int c0 = 8 * nt + 2 * tig;
            float4 p0 = sPack[c0], p1 = sPack[c0 + 1];
            float2 bp0 = unpack_bf16(bpbf[jr0 * 128 + 4 * nt + tig]);
            float2 bp1 = unpack_bf16(bpbf[jr1 * 128 + 4 * nt + tig]);
            float v00 = acc[ntl][0] + p0.x + sx0 * p0.y + sya0 * p0.z + sys0 * p0.w + bp0.x;
            float v01 = acc[ntl][1] + p1.x + sx0 * p1.y + sya0 * p1.z + sys0 * p1.w + bp0.y;
            float v10 = acc[ntl][2] + p0.x + sx1 * p0.y + sya1 * p0.z + sys1 * p0.w + bp1.x;
            float v11 = acc[ntl][3] + p1.x + sx1 * p1.y + sya1 * p1.z + sys1 * p1.w + bp1.y;
            v00 = fmaxf(v00, 0.f); v01 = fmaxf(v01, 0.f);
            v10 = fmaxf(v10, 0.f); v11 = fmaxf(v11, 0.f);
            sum0 += v00 + v01; sq0 += v00 * v00 + v01 * v01;
            sum1 += v10 + v11; sq1 += v10 * v10 + v11 * v11;
            int q2 = nt >> 1, off = (nt & 1) * 2;
            H1[4 * q2 + off]     = pack_bf16(v00, v01);
            H1[4 * q2 + off + 1] = pack_bf16(v10, v11);
        }
    }

    // ================= layernorm (quad-local) ================================
#pragma unroll
    for (int o = 1; o <= 2; o <<= 1) {
        sum0 += __shfl_xor_sync(0xffffffffu, sum0, o);
        sq0  += __shfl_xor_sync(0xffffffffu, sq0,  o);
        sum1 += __shfl_xor_sync(0xffffffffu, sum1, o);
        sq1  += __shfl_xor_sync(0xffffffffu, sq1,  o);
    }
    float mu0 = sum0 * (1.f / 256.f);
    float rs0 = rsqrtf(sq0 * (1.f / 256.f) - mu0 * mu0 + 1e-5f);
    float mu1 = sum1 * (1.f / 256.f);
    float rs1 = rsqrtf(sq1 * (1.f / 256.f) - mu1 * mu1 + 1e-5f);
#pragma unroll
    for (int q = 0; q < 16; q++) {
#pragma unroll
        for (int e2 = 0; e2 < 2; e2++) {
            int col = 16 * q + 8 * e2 + 2 * tig;
            float2 gb0 = sLgb[col], gb1 = sLgb[col + 1];
#pragma unroll
            for (int e = 0; e < 2; e++) {
                int idx = 4 * q + 2 * e2 + e;
                float2 v = unpack_bf16(H1[idx]);
                float m = e ? mu1 : mu0, rr = e ? rs1 : rs0;
                H1[idx] = pack_bf16((v.x - m) * rr * gb0.x + gb0.y,
                                    (v.y - m) * rr * gb1.x + gb1.y);
            }
        }
    }

    // ================= layer 2 (bf16): N=128, K=256 ==========================
    uint32_t H2[32];
#pragma unroll
    for (int h = 0; h < 2; h++) {
        float acc[8][4];
#pragma unroll
        for (int ntl = 0; ntl < 8; ntl++)
#pragma unroll
            for (int q = 0; q < 4; q++) acc[ntl][q] = 0.f;
#pragma unroll
        for (int q = 0; q < 16; q++) {
            uint32_t a0 = H1[4 * q],     a1 = H1[4 * q + 1];
            uint32_t a2 = H1[4 * q + 2], a3 = H1[4 * q + 3];
#pragma unroll
            for (int ntl = 0; ntl < 8; ntl++) {
                int n = (h * 8 + ntl) * 8 + g;
                uint32_t b0 = W2s[n * 132 + 8 * q + tig];
                uint32_t b1 = W2s[n * 132 + 8 * q + 4 + tig];
                mma_bf16(acc[ntl], a0, a1, a2, a3, b0, b1);
            }
        }
#pragma unroll
        for (int ntl = 0; ntl < 8; ntl++) {
            int nt = h * 8 + ntl;
            int c0 = 8 * nt + 2 * tig;
            float v00 = fmaxf(acc[ntl][0] + sB2[c0], 0.f);
            float v01 = fmaxf(acc[ntl][1] + sB2[c0 + 1], 0.f);
            float v10 = fmaxf(acc[ntl][2] + sB2[c0], 0.f);
            float v11 = fmaxf(acc[ntl][3] + sB2[c0 + 1], 0.f);
            int q2 = nt >> 1, off = (nt & 1) * 2;
            H2[4 * q2 + off]     = pack_bf16(v00, v01);
            H2[4 * q2 + off + 1] = pack_bf16(v10, v11);
        }
    }

    // ================= layer 3 (bf16): N=64, K=128 ===========================
    uint32_t H3[16];
    {
        float acc[8][4];
#pragma unroll
        for (int ntl = 0; ntl < 8; ntl++)
#pragma unroll
            for (int q = 0; q < 4; q++) acc[ntl][q] = 0.f;
#pragma unroll
        for (int q = 0; q < 8; q++) {
            uint32_t a0 = H2[4 * q],     a1 = H2[4 * q + 1];
            uint32_t a2 = H2[4 * q + 2], a3 = H2[4 * q + 3];
#pragma unroll
            for (int ntl = 0; ntl < 8; ntl++) {
                int n = ntl * 8 + g;
                uint32_t b0 = W3s[n * 68 + 8 * q + tig];
                uint32_t b1 = W3s[n * 68 + 8 * q + 4 + tig];
                mma_bf16(acc[ntl], a0, a1, a2, a3, b0, b1);
            }
        }
#pragma unroll
        for (int nt = 0; nt < 8; nt++) {
            int c0 = 8 * nt + 2 * tig;
            float v00 = fmaxf(acc[nt][0] + sB3[c0], 0.f);
            float v01 = fmaxf(acc[nt][1] + sB3[c0 + 1], 0.f);
            float v10 = fmaxf(acc[nt][2] + sB3[c0], 0.f);
            float v11 = fmaxf(acc[nt][3] + sB3[c0 + 1], 0.f);
            int q2 = nt >> 1, off = (nt & 1) * 2;
            H3[4 * q2 + off]     = pack_bf16(v00, v01);
            H3[4 * q2 + off + 1] = pack_bf16(v10, v11);
        }
    }

    // ================= layer 4 (bf16) + layer 5 dot ==========================
    {
        float acc[4][4];
#pragma unroll
        for (int ntl = 0; ntl < 4; ntl++)
#pragma unroll
            for (int q = 0; q < 4; q++) acc[ntl][q] = 0.f;
#pragma unroll
        for (int q = 0; q < 4; q++) {
            uint32_t a0 = H3[4 * q],     a1 = H3[4 * q + 1];
            uint32_t a2 = H3[4 * q + 2], a3 = H3[4 * q + 3];
#pragma unroll
            for (int ntl = 0; ntl < 4; ntl++) {
                int n = ntl * 8 + g;
                uint32_t b0 = W4s[n * 36 + 8 * q + tig];
                uint32_t b1 = W4s[n * 36 + 8 * q + 4 + tig];
                mma_bf16(acc[ntl], a0, a1, a2, a3, b0, b1);
            }
        }
        float p0 = 0.f, p1 = 0.f;
#pragma unroll
        for (int nt = 0; nt < 4; nt++) {
            int c0 = 8 * nt + 2 * tig;
            p0 += fmaxf(acc[nt][0] + sB4[c0], 0.f) * sW5[c0]
                + fmaxf(acc[nt][1] + sB4[c0 + 1], 0.f) * sW5[c0 + 1];
            p1 += fmaxf(acc[nt][2] + sB4[c0], 0.f) * sW5[c0]
                + fmaxf(acc[nt][3] + sB4[c0 + 1], 0.f) * sW5[c0 + 1];
        }
#pragma unroll
        for (int o = 1; o <= 2; o <<= 1) {
            p0 += __shfl_xor_sync(0xffffffffu, p0, o);
            p1 += __shfl_xor_sync(0xffffffffu, p1, o);
        }
        if (tig == 0) {
            float bb = sB5[0];
            out[i * 768 + jr0] = (jr0 == i) ? -1000000000.0f : p0 + bb;
            out[i * 768 + jr1] = (jr1 == i) ? -1000000000.0f : p1 + bb;
        }
    }
}

// ---------------- host launch ------------------------------------------------
extern "C" void kernel_launch(void* const* d_in, const int* in_sizes, int n_in,
                              void* d_out, int out_size)
{
    (void)in_sizes; (void)n_in; (void)out_size;
    const float* features = (const float*)d_in[0];
    const float* boxes    = (const float*)d_in[1];
    const float* in_w     = (const float*)d_in[2];
    const float* in_b     = (const float*)d_in[3];
    const float* out_w    = (const float*)d_in[4];
    const float* out_b    = (const float*)d_in[5];
    const float* w1       = (const float*)d_in[6];
    const float* b1       = (const float*)d_in[7];
    const float* lng      = (const float*)d_in[8];
    const float* lnb      = (const float*)d_in[9];
    const float* w2       = (const float*)d_in[10];
    const float* b2       = (const float*)d_in[11];
    const float* w3       = (const float*)d_in[12];
    const float* b3       = (const float*)d_in[13];
    const float* w4       = (const float*)d_in[14];
    const float* b4       = (const float*)d_in[15];
    const float* w5       = (const float*)d_in[16];
    const float* b5       = (const float*)d_in[17];
    float* out = (float*)d_out;

    void *featbf, *inwbf, *outwbf, *w1abf, *w1bbf, *w1cf8, *w2bf, *w3bf, *w4bf;
    void *qkvbf, *obf, *attbf, *bpbf;
    float* Apb;
    cudaGetSymbolAddress(&featbf, g_feat_bf);
    cudaGetSymbolAddress(&inwbf,  g_inw_bf);
    cudaGetSymbolAddress(&outwbf, g_outw_bf);
    cudaGetSymbolAddress(&w1abf,  g_w1a_bf);
    cudaGetSymbolAddress(&w1bbf,  g_w1b_bf);
    cudaGetSymbolAddress(&w1cf8,  g_w1c_f8);
    cudaGetSymbolAddress(&w2bf,   g_w2_bf);
    cudaGetSymbolAddress(&w3bf,   g_w3_bf);
    cudaGetSymbolAddress(&w4bf,   g_w4_bf);
    cudaGetSymbolAddress(&qkvbf,  g_qkv_bf);
    cudaGetSymbolAddress(&obf,    g_o_bf);
    cudaGetSymbolAddress(&attbf,  g_att_bf);
    cudaGetSymbolAddress(&bpbf,   g_Bp_bf);
    cudaGetSymbolAddress((void**)&Apb, g_Ap);

    cudaFuncSetAttribute(gemm_bf256,
                         cudaFuncAttributeMaxDynamicSharedMemorySize, GEMM_SMEM_BYTES);
    cudaFuncSetAttribute(fused_pairs_reg,
                         cudaFuncAttributeMaxDynamicSharedMemorySize, SMEM_BYTES);

    convert_pre<<<768, 256>>>(features, in_w, out_w, w1, w2, w3, w4);

    gemm_bf256<<<dim3(6, 12), 128, GEMM_SMEM_BYTES>>>(
        (const uint4*)featbf, (const uint4*)inwbf, in_b,
        nullptr, (uint32_t*)qkvbf, 768);

    build_vT<<<256, 256>>>();

    attn_flash<<<dim3(12, 8), 128>>>(nullptr);

    gemm_bf256<<<dim3(2, 12), 128, GEMM_SMEM_BYTES>>>(
        (const uint4*)obf, (const uint4*)outwbf, out_b,
        nullptr, (uint32_t*)attbf, 256);

    gemm_bf256<<<dim3(2, 12), 128, GEMM_SMEM_BYTES>>>(
        (const uint4*)attbf, (const uint4*)w1abf, b1,
        Apb, nullptr, 256);

    gemm_bf256<<<dim3(2, 12), 128, GEMM_SMEM_BYTES>>>(
        (const uint4*)attbf, (const uint4*)w1bbf, nullptr,
        nullptr, (uint32_t*)bpbf, 256);

    fused_pairs_reg<<<dim3(6, 768), 256, SMEM_BYTES>>>(
        boxes, w1, Apb,
        (const uint32_t*)attbf, (const uint32_t*)bpbf,
        (const uint4*)w1cf8, (const uint4*)w2bf,
        (const uint4*)w3bf, (const uint4*)w4bf,
        lng, lnb, b2, b3, b4, w5, b5, out);
}

// round 8
// speedup vs baseline: 1.1383x; 1.1383x over previous
#include <cuda_runtime.h>
#include <cuda_bf16.h>
#include <cstdint>
#include <math.h>

#define NTOK 768
#define DMODEL 256
#define NHEAD 8

// ---------------- scratch (device globals; no allocations allowed) ----------
__device__ __nv_bfloat16 g_feat_bf[NTOK * DMODEL];
__device__ __nv_bfloat16 g_inw_bf[768 * 256];
__device__ __nv_bfloat16 g_outwT_bf[256 * 256];    // [e][d] = out_w[d][e]
__device__ __nv_bfloat16 g_w1ab_bf[512 * 256];     // rows 0-255 w1a, 256-511 w1b
__device__ __nv_bfloat16 g_w1c_bf[256 * 256];
__device__ __nv_bfloat16 g_w2_bf[128 * 256];
__device__ __nv_bfloat16 g_w3_bf[64 * 128];
__device__ __nv_bfloat16 g_w4_bf[32 * 64];
__device__ __nv_bfloat16 g_qkv_bf[NTOK * 768];
__device__ __nv_bfloat16 g_vT_bf[NHEAD * 32 * NTOK];
__device__ __nv_bfloat16 g_o_bf[NTOK * DMODEL];
__device__ __nv_bfloat16 g_att_bf[NTOK * DMODEL];
__device__ __nv_bfloat16 g_Bp_bf[NTOK * DMODEL];
__device__ float g_Ap[NTOK * DMODEL];
__device__ __nv_bfloat16 g_bigB_bf[768 * 256];     // rows 0-255 out_w; 256-767 Mab
__device__ float g_bigbias[768];                    // out_b | ba | bb

// ---------------- helpers ----------------------------------------------------
__device__ __forceinline__ void mma_bf16(float* c, unsigned a0, unsigned a1,
                                         unsigned a2, unsigned a3,
                                         unsigned b0, unsigned b1)
{
    asm volatile(
        "mma.sync.aligned.m16n8k16.row.col.f32.bf16.bf16.f32 "
        "{%0,%1,%2,%3}, {%4,%5,%6,%7}, {%8,%9}, {%0,%1,%2,%3};"
        : "+f"(c[0]), "+f"(c[1]), "+f"(c[2]), "+f"(c[3])
        : "r"(a0), "r"(a1), "r"(a2), "r"(a3), "r"(b0), "r"(b1));
}
__device__ __forceinline__ unsigned pack_bf16(float a, float b)
{
    __nv_bfloat162 h;
    h.x = __float2bfloat16_rn(a);
    h.y = __float2bfloat16_rn(b);
    return *reinterpret_cast<unsigned*>(&h);
}
__device__ __forceinline__ float2 unpack_bf16(unsigned u)
{
    __nv_bfloat162 h = *reinterpret_cast<__nv_bfloat162*>(&u);
    return make_float2(__bfloat162float(h.x), __bfloat162float(h.y));
}
__device__ __forceinline__ float fexp2(float x)
{
    float y;
    asm("ex2.approx.ftz.f32 %0, %1;" : "=f"(y) : "f"(x));
    return y;
}

// ---------------- conversions + bias prep ------------------------------------
__global__ void convert_pre(const float* __restrict__ features,
                            const float* __restrict__ in_w,
                            const float* __restrict__ out_w,
                            const float* __restrict__ out_b,
                            const float* __restrict__ w1,
                            const float* __restrict__ b1,
                            const float* __restrict__ w2,
                            const float* __restrict__ w3,
                            const float* __restrict__ w4)
{
    int t = blockIdx.x * 256 + threadIdx.x;
    if (t < 196608) {
        g_feat_bf[t] = __float2bfloat16_rn(features[t]);
        g_inw_bf[t]  = __float2bfloat16_rn(in_w[t]);
    }
    if (t < 65536) {
        int n = t >> 8, d = t & 255;
        g_bigB_bf[t]  = __float2bfloat16_rn(out_w[t]);           // out_w rows
        g_outwT_bf[t] = __float2bfloat16_rn(out_w[d * 256 + n]); // transpose
        g_w1ab_bf[t]          = __float2bfloat16_rn(w1[n * 771 + d]);
        g_w1ab_bf[65536 + t]  = __float2bfloat16_rn(w1[n * 771 + 256 + d]);
        g_w1c_bf[t]           = __float2bfloat16_rn(w1[n * 771 + 512 + d]);
    }
    if (t < 32768) g_w2_bf[t] = __float2bfloat16_rn(w2[t]);
    if (t < 8192)  g_w3_bf[t] = __float2bfloat16_rn(w3[t]);
    if (t < 2048)  g_w4_bf[t] = __float2bfloat16_rn(w4[t]);
    // bias prep: bigbias = [out_b | w1a.out_b + b1 | w1b.out_b]
    if (t < 256) g_bigbias[t] = out_b[t];
    else if (t < 768) {
        int k = (t - 256) & 255;
        int off = (t < 512) ? 0 : 256;     // w1a vs w1b columns
        float s = 0.f;
        for (int d = 0; d < 256; d++) s += w1[k * 771 + off + d] * out_b[d];
        if (t < 512) s += b1[k];
        g_bigbias[t] = s;
    }
}

// ---------------- unified bf16 GEMM, K=256, 128x128 tile, 256 threads --------
// mode 0: Cb = out_a (pitch N/2 u32), bias optional
// mode 1: qkv: out_a + vT scatter for gn>=512 (vt = g_vT_bf)
// mode 2: merged: gn<256 -> out_a(att), 256-511 -> out_f(Ap fp32), >=512 -> out_b2(Bp)
#define GEMM_SMEM_U32 33792
#define GEMM_SMEM_BYTES (GEMM_SMEM_U32 * 4)

__global__ __launch_bounds__(256, 1) void gemm_k256(
    const uint4* __restrict__ A4, const uint4* __restrict__ B4,
    const float* __restrict__ bias, int N, int mode,
    uint32_t* __restrict__ out_a, float* __restrict__ out_f,
    uint32_t* __restrict__ out_b2, __nv_bfloat16* __restrict__ vt)
{
    extern __shared__ uint32_t sg[];
    uint32_t* As = sg;              // 128 x 132
    uint32_t* Bs = sg + 16896;

    const int m0 = blockIdx.y * 128;
    const int n0 = blockIdx.x * 128;
    const int t  = threadIdx.x;
    const int w  = t >> 5;
    const int lane = t & 31;
    const int g   = lane >> 2;
    const int tig = lane & 3;
    const int r0i = w * 16 + g, r1i = r0i + 8;

    for (int idx = t; idx < 4096; idx += 256) {
        int r = idx >> 5, c4 = idx & 31;
        *(uint4*)&As[r * 132 + c4 * 4] = A4[(m0 + r) * 32 + c4];
        *(uint4*)&Bs[r * 132 + c4 * 4] = B4[(n0 + r) * 32 + c4];
    }
    __syncthreads();

    float acc[16][4];
#pragma unroll
    for (int nt = 0; nt < 16; nt++)
#pragma unroll
        for (int q = 0; q < 4; q++) acc[nt][q] = 0.f;

#pragma unroll
    for (int q = 0; q < 16; q++) {
        uint32_t a0 = As[r0i * 132 + 8 * q + tig];
        uint32_t a1 = As[r1i * 132 + 8 * q + tig];
        uint32_t a2 = As[r0i * 132 + 8 * q + 4 + tig];
        uint32_t a3 = As[r1i * 132 + 8 * q + 4 + tig];
#pragma unroll
        for (int nt = 0; nt < 16; nt++) {
            int n = 8 * nt + g;
            uint32_t b0 = Bs[n * 132 + 8 * q + tig];
            uint32_t b1 = Bs[n * 132 + 8 * q + 4 + tig];
            mma_bf16(acc[nt], a0, a1, a2, a3, b0, b1);
        }
    }

    const int gm0 = m0 + r0i, gm1 = m0 + r1i;
#pragma unroll
    for (int nt = 0; nt < 16; nt++) {
        int gn = n0 + 8 * nt + 2 * tig;
        float bi0 = bias ? bias[gn] : 0.f;
        float bi1 = bias ? bias[gn + 1] : 0.f;
        float v00 = acc[nt][0] + bi0, v01 = acc[nt][1] + bi1;
        float v10 = acc[nt][2] + bi0, v11 = acc[nt][3] + bi1;
        if (mode == 2) {
            if (gn < 256) {
                out_a[gm0 * 128 + (gn >> 1)] = pack_bf16(v00, v01);
                out_a[gm1 * 128 + (gn >> 1)] = pack_bf16(v10, v11);
            } else if (gn < 512) {
                *(float2*)&out_f[gm0 * 256 + (gn - 256)] = make_float2(v00, v01);
                *(float2*)&out_f[gm1 * 256 + (gn - 256)] = make_float2(v10, v11);
            } else {
                out_b2[gm0 * 128 + ((gn - 512) >> 1)] = pack_bf16(v00, v01);
                out_b2[gm1 * 128 + ((gn - 512) >> 1)] = pack_bf16(v10, v11);
            }
        } else {
            out_a[gm0 * (N >> 1) + (gn >> 1)] = pack_bf16(v00, v01);
            out_a[gm1 * (N >> 1) + (gn >> 1)] = pack_bf16(v10, v11);
            if (mode == 1 && gn >= 512) {
                int vr = gn - 512;
                vt[vr * 768 + gm0]       = __float2bfloat16_rn(v00);
                vt[(vr + 1) * 768 + gm0] = __float2bfloat16_rn(v01);
                vt[vr * 768 + gm1]       = __float2bfloat16_rn(v10);
                vt[(vr + 1) * 768 + gm1] = __float2bfloat16_rn(v11);
            }
        }
    }
}

// ---------------- flash attention (R6 config: 128-row q tiles, 256 thr) ------
__global__ __launch_bounds__(256, 1) void attn_flash()
{
    __shared__ uint32_t Ks[128 * 20];
    __shared__ uint32_t VTs[32 * 68];

    const int q0 = blockIdx.x * 128;
    const int h  = blockIdx.y;
    const int t  = threadIdx.x;
    const int w  = t >> 5;
    const int lane = t & 31;
    const int g   = lane >> 2;
    const int tig = lane & 3;
    const int r0i = w * 16 + g, r1i = r0i + 8;

    const uint32_t* qkvU = (const uint32_t*)g_qkv_bf;
    const uint32_t* vtU  = (const uint32_t*)g_vT_bf;

    const float CS = 1.4426950408889634f * 0.17677669529663687f;

    uint32_t qf[8];
#pragma unroll
    for (int qq = 0; qq < 2; qq++) {
        qf[4 * qq]     = qkvU[(q0 + r0i) * 384 + h * 16 + 8 * qq + tig];
        qf[4 * qq + 1] = qkvU[(q0 + r1i) * 384 + h * 16 + 8 * qq + tig];
        qf[4 * qq + 2] = qkvU[(q0 + r0i) * 384 + h * 16 + 8 * qq + 4 + tig];
        qf[4 * qq + 3] = qkvU[(q0 + r1i) * 384 + h * 16 + 8 * qq + 4 + tig];
    }

    float acc_o[4][4];
#pragma unroll
    for (int nt = 0; nt < 4; nt++)
#pragma unroll
        for (int e = 0; e < 4; e++) acc_o[nt][e] = 0.f;
    float m0s = -1e30f, m1s = -1e30f, l0p = 0.f, l1p = 0.f;

    for (int kt = 0; kt < 6; kt++) {
        __syncthreads();
        for (int idx = t; idx < 2048; idx += 256) {
            int r = idx >> 4, c = idx & 15;
            Ks[r * 20 + c] = qkvU[(kt * 128 + r) * 384 + 128 + h * 16 + c];
        }
        for (int idx = t; idx < 2048; idx += 256) {
            int d = idx >> 6, c = idx & 63;
            VTs[d * 68 + c] = vtU[(h * 32 + d) * 384 + kt * 64 + c];
        }
        __syncthreads();

        float accs[16][4];
#pragma unroll
        for (int nt = 0; nt < 16; nt++)
#pragma unroll
            for (int e = 0; e < 4; e++) accs[nt][e] = 0.f;
#pragma unroll
        for (int qq = 0; qq < 2; qq++) {
            uint32_t a0 = qf[4 * qq], a1 = qf[4 * qq + 1];
            uint32_t a2 = qf[4 * qq + 2], a3 = qf[4 * qq + 3];
#pragma unroll
            for (int nt = 0; nt < 16; nt++) {
                int n = 8 * nt + g;
                uint32_t b0 = Ks[n * 20 + 8 * qq + tig];
                uint32_t b1 = Ks[n * 20 + 8 * qq + 4 + tig];
                mma_bf16(accs[nt], a0, a1, a2, a3, b0, b1);
            }
        }
        float lm0 = -1e30f, lm1 = -1e30f;
#pragma unroll
        for (int nt = 0; nt < 16; nt++) {
            accs[nt][0] *= CS; accs[nt][1] *= CS;
            accs[nt][2] *= CS; accs[nt][3] *= CS;
            lm0 = fmaxf(lm0, fmaxf(accs[nt][0], accs[nt][1]));
            lm1 = fmaxf(lm1, fmaxf(accs[nt][2], accs[nt][3]));
        }
#pragma unroll
        for (int o = 1; o <= 2; o <<= 1) {
            lm0 = fmaxf(lm0, __shfl_xor_sync(0xffffffffu, lm0, o));
            lm1 = fmaxf(lm1, __shfl_xor_sync(0xffffffffu, lm1, o));
        }
        float mn0 = fmaxf(m0s, lm0), mn1 = fmaxf(m1s, lm1);
        float al0 = fexp2(m0s - mn0), al1 = fexp2(m1s - mn1);
        m0s = mn0; m1s = mn1;

        float ps0 = 0.f, ps1 = 0.f;
        uint32_t Pf[32];
#pragma unroll
        for (int nt = 0; nt < 16; nt++) {
            float p00 = fexp2(accs[nt][0] - mn0);
            float p01 = fexp2(accs[nt][1] - mn0);
            float p10 = fexp2(accs[nt][2] - mn1);
            float p11 = fexp2(accs[nt][3] - mn1);
            ps0 += p00 + p01; ps1 += p10 + p11;
            int q2 = nt >> 1, off = (nt & 1) * 2;
            Pf[4 * q2 + off]     = pack_bf16(p00, p01);
            Pf[4 * q2 + off + 1] = pack_bf16(p10, p11);
        }
        l0p = l0p * al0 + ps0;
        l1p = l1p * al1 + ps1;
#pragma unroll
        for (int nt = 0; nt < 4; nt++) {
            acc_o[nt][0] *= al0; acc_o[nt][1] *= al0;
            acc_o[nt][2] *= al1; acc_o[nt][3] *= al1;
        }
#pragma unroll
        for (int q = 0; q < 8; q++) {
            uint32_t a0 = Pf[4 * q], a1 = Pf[4 * q + 1];
            uint32_t a2 = Pf[4 * q + 2], a3 = Pf[4 * q + 3];
#pragma unroll
            for (int nt = 0; nt < 4; nt++) {
                int n = 8 * nt + g;
                uint32_t b0 = VTs[n * 68 + 8 * q + tig];
                uint32_t b1 = VTs[n * 68 + 8 * q + 4 + tig];
                mma_bf16(acc_o[nt], a0, a1, a2, a3, b0, b1);
            }
        }
    }

#pragma unroll
    for (int o = 1; o <= 2; o <<= 1) {
        l0p += __shfl_xor_sync(0xffffffffu, l0p, o);
        l1p += __shfl_xor_sync(0xffffffffu, l1p, o);
    }
    float inv0 = 1.f / l0p, inv1 = 1.f / l1p;
    uint32_t* oU = (uint32_t*)g_o_bf;
#pragma unroll
    for (int nt = 0; nt < 4; nt++) {
        oU[(q0 + r0i) * 128 + h * 16 + 4 * nt + tig] =
            pack_bf16(acc_o[nt][0] * inv0, acc_o[nt][1] * inv0);
        oU[(q0 + r1i) * 128 + h * 16 + 4 * nt + tig] =
            pack_bf16(acc_o[nt][2] * inv1, acc_o[nt][3] * inv1);
    }
}

// ---------------- fused all-pairs MLP (R5/R6 proven, bf16 all layers) --------
#define OFF_W1   0
#define OFF_W2   33792
#define OFF_W3   50688
#define OFF_W4   55040
#define OFF_PACK 56192
#define OFF_LGB  57216
#define OFF_B2   57728
#define OFF_B3   57856
#define OFF_B4   57920
#define OFF_W5   57952
#define OFF_B5   57984
#define SMEM_U32 57988
#define SMEM_BYTES (SMEM_U32 * 4)

__global__ __launch_bounds__(256, 1) void fused_pairs_reg(
    const float* __restrict__ boxes,
    const float* __restrict__ w1,
    const float* __restrict__ Ap,
    const uint32_t* __restrict__ attbf,
    const uint32_t* __restrict__ bpbf,
    const uint4* __restrict__ w1v, const uint4* __restrict__ w2v,
    const uint4* __restrict__ w3v, const uint4* __restrict__ w4v,
    const float* __restrict__ lng, const float* __restrict__ lnb,
    const float* __restrict__ b2, const float* __restrict__ b3,
    const float* __restrict__ b4,
    const float* __restrict__ w5, const float* __restrict__ b5,
    float* __restrict__ out)
{
    extern __shared__ uint32_t sm[];
    uint32_t* W1s = sm + OFF_W1;
    uint32_t* W2s = sm + OFF_W2;
    uint32_t* W3s = sm + OFF_W3;
    uint32_t* W4s = sm + OFF_W4;
    float4*   sPack = (float4*)(sm + OFF_PACK);
    float2*   sLgb  = (float2*)(sm + OFF_LGB);
    float*    sB2   = (float*)(sm + OFF_B2);
    float*    sB3   = (float*)(sm + OFF_B3);
    float*    sB4   = (float*)(sm + OFF_B4);
    float*    sW5   = (float*)(sm + OFF_W5);
    float*    sB5   = (float*)(sm + OFF_B5);

    const int i  = blockIdx.y;
    const int j0 = blockIdx.x * 128;
    const int t  = threadIdx.x;
    const int w  = t >> 5;
    const int lane = t & 31;
    const int g   = lane >> 2;
    const int tig = lane & 3;

    for (int idx = t; idx < 8192; idx += 256) {
        int r = idx >> 5, c4 = idx & 31;
        *(uint4*)&W1s[r * 132 + c4 * 4] = w1v[idx];
    }
    for (int idx = t; idx < 4096; idx += 256) {
        int r = idx >> 5, c4 = idx & 31;
        *(uint4*)&W2s[r * 132 + c4 * 4] = w2v[idx];
    }
    for (int idx = t; idx < 1024; idx += 256) {
        int r = idx >> 4, c4 = idx & 15;
        *(uint4*)&W3s[r * 68 + c4 * 4] = w3v[idx];
    }
    for (int idx = t; idx < 256; idx += 256) {
        int r = idx >> 3, c4 = idx & 7;
        *(uint4*)&W4s[r * 36 + c4 * 4] = w4v[idx];
    }
    {
        int k = t;
        sPack[k] = make_float4(Ap[i * 256 + k], w1[k * 771 + 768],
                               w1[k * 771 + 769], w1[k * 771 + 770]);
        sLgb[k]  = make_float2(lng[k], lnb[k]);
        if (k < 128) sB2[k] = b2[k];
        if (k < 64)  sB3[k] = b3[k];
        if (k < 32)  { sB4[k] = b4[k]; sW5[k] = w5[k]; }
        if (k == 0)  sB5[0] = b5[0];
    }
    __syncthreads();

    const int r0 = w * 16 + g, r1 = r0 + 8;
    const int jr0 = j0 + r0, jr1 = j0 + r1;

    float bxi = boxes[i * 4], byi = boxes[i * 4 + 1];
    float dy0 = byi - boxes[jr0 * 4 + 1];
    float dy1 = byi - boxes[jr1 * 4 + 1];
    float sx0 = fabsf(bxi - boxes[jr0 * 4]), sya0 = fabsf(dy0), sys0 = dy0;
    float sx1 = fabsf(bxi - boxes[jr1 * 4]), sya1 = fabsf(dy1), sys1 = dy1;

    uint32_t A1[64];
#pragma unroll
    for (int q = 0; q < 16; q++) {
        int p0 = 8 * q + tig, p1 = p0 + 4;
        float2 ai0 = unpack_bf16(attbf[i * 128 + p0]);
        float2 ai1 = unpack_bf16(attbf[i * 128 + p1]);
        float2 j00 = unpack_bf16(attbf[jr0 * 128 + p0]);
        float2 j10 = unpack_bf16(attbf[jr1 * 128 + p0]);
        float2 j01 = unpack_bf16(attbf[jr0 * 128 + p1]);
        float2 j11 = unpack_bf16(attbf[jr1 * 128 + p1]);
        A1[4 * q]     = pack_bf16(j00.x * ai0.x, j00.y * ai0.y);
        A1[4 * q + 1] = pack_bf16(j10.x * ai0.x, j10.y * ai0.y);
        A1[4 * q + 2] = pack_bf16(j01.x * ai1.x, j01.y * ai1.y);
        A1[4 * q + 3] = pack_bf16(j11.x * ai1.x, j11.y * ai1.y);
    }

    uint32_t H1[64];
    float sum0 = 0.f, sq0 = 0.f, sum1 = 0.f, sq1 = 0.f;
#pragma unroll
    for (int h = 0; h < 2; h++) {
        float acc[16][4];
#pragma unroll
        for (int ntl = 0; ntl < 16; ntl++)
#pragma unroll
            for (int q = 0; q < 4; q++) acc[ntl][q] = 0.f;

#pragma unroll
        for (int q = 0; q < 16; q++) {
            uint32_t a0 = A1[4 * q],     a1 = A1[4 * q + 1];
            uint32_t a2 = A1[4 * q + 2], a3 = A1[4 * q + 3];
#pragma unroll
            for (int ntl = 0; ntl < 16; ntl++) {
                int n = (h * 16 + ntl) * 8 + g;
                uint32_t b0 = W1s[n * 132 + 8 * q + tig];
                uint32_t b1 = W1s[n * 132 + 8 * q + 4 + tig];
                mma_bf16(acc[ntl], a0, a1, a2, a3, b0, b1);
            }
        }
#pragma unroll
        for (int ntl = 0; ntl < 16; ntl++) {
            int nt = h * 16 + ntl;
            int c0 = 8 * nt + 2 * tig;
            float4 p0 = sPack[c0], p1 = sPack[c0 + 1];
            float2 bp0 = unpack_bf16(bpbf[jr0 * 128 + 4 * nt + tig]);
            float2 bp1 = unpack_bf16(bpbf[jr1 * 128 + 4 * nt + tig]);
            float v00 = acc[ntl][0] + p0.x + sx0 * p0.y + sya0 * p0.z + sys0 * p0.w + bp0.x;
            float v01 = acc[ntl][1] + p1.x + sx0 * p1.y + sya0 * p1.z + sys0 * p1.w + bp0.y;
            float v10 = acc[ntl][2] + p0.x + sx1 * p0.y + sya1 * p0.z + sys1 * p0.w + bp1.x;
            float v11 = acc[ntl][3] + p1.x + sx1 * p1.y + sya1 * p1.z + sys1 * p1.w + bp1.y;
            v00 = fmaxf(v00, 0.f); v01 = fmaxf(v01, 0.f);
            v10 = fmaxf(v10, 0.f); v11 = fmaxf(v11, 0.f);
            sum0 += v00 + v01; sq0 += v00 * v00 + v01 * v01;
            sum1 += v10 + v11; sq1 += v10 * v10 + v11 * v11;
            int q2 = nt >> 1, off = (nt & 1) * 2;
            H1[4 * q2 + off]     = pack_bf16(v00, v01);
            H1[4 * q2 + off + 1] = pack_bf16(v10, v11);
        }
    }

#pragma unroll
    for (int o = 1; o <= 2; o <<= 1) {
        sum0 += __shfl_xor_sync(0xffffffffu, sum0, o);
        sq0  += __shfl_xor_sync(0xffffffffu, sq0,  o);
        sum1 += __shfl_xor_sync(0xffffffffu, sum1, o);
        sq1  += __shfl_xor_sync(0xffffffffu, sq1,  o);
    }
    float mu0 = sum0 * (1.f / 256.f);
    float rs0 = rsqrtf(sq0 * (1.f / 256.f) - mu0 * mu0 + 1e-5f);
    float mu1 = sum1 * (1.f / 256.f);
    float rs1 = rsqrtf(sq1 * (1.f / 256.f) - mu1 * mu1 + 1e-5f);
#pragma unroll
    for (int q = 0; q < 16; q++) {
#pragma unroll
        for (int e2 = 0; e2 < 2; e2++) {
            int col = 16 * q + 8 * e2 + 2 * tig;
            float2 gb0 = sLgb[col], gb1 = sLgb[col + 1];
#pragma unroll
            for (int e = 0; e < 2; e++) {
                int idx = 4 * q + 2 * e2 + e;
                float2 v = unpack_bf16(H1[idx]);
                float m = e ? mu1 : mu0, rr = e ? rs1 : rs0;
                H1[idx] = pack_bf16((v.x - m) * rr * gb0.x + gb0.y,
                                    (v.y - m) * rr * gb1.x + gb1.y);
            }
        }
    }

    uint32_t H2[32];
#pragma unroll
    for (int h = 0; h < 2; h++) {
        float acc[8][4];
#pragma unroll
        for (int ntl = 0; ntl < 8; ntl++)
#pragma unroll
            for (int q = 0; q < 4; q++) acc[ntl][q] = 0.f;
#pragma unroll
        for (int q = 0; q < 16; q++) {
            uint32_t a0 = H1[4 * q],     a1 = H1[4 * q + 1];
            uint32_t a2 = H1[4 * q + 2], a3 = H1[4 * q + 3];
#pragma unroll
            for (int ntl = 0; ntl < 8; ntl++) {
                int n = (h * 8 + ntl) * 8 + g;
                uint32_t b0 = W2s[n * 132 + 8 * q + tig];
                uint32_t b1 = W2s[n * 132 + 8 * q + 4 + tig];
                mma_bf16(acc[ntl], a0, a1, a2, a3, b0, b1);
            }
        }
#pragma unroll
        for (int ntl = 0; ntl < 8; ntl++) {
            int nt = h * 8 + ntl;
            int c0 = 8 * nt + 2 * tig;
            float v00 = fmaxf(acc[ntl][0] + sB2[c0], 0.f);
            float v01 = fmaxf(acc[ntl][1] + sB2[c0 + 1], 0.f);
            float v10 = fmaxf(acc[ntl][2] + sB2[c0], 0.f);
            float v11 = fmaxf(acc[ntl][3] + sB2[c0 + 1], 0.f);
            int q2 = nt >> 1, off = (nt & 1) * 2;
            H2[4 * q2 + off]     = pack_bf16(v00, v01);
            H2[4 * q2 + off + 1] = pack_bf16(v10, v11);
        }
    }

    uint32_t H3[16];
    {
        float acc[8][4];
#pragma unroll
        for (int ntl = 0; ntl < 8; ntl++)
#pragma unroll
            for (int q = 0; q < 4; q++) acc[ntl][q] = 0.f;
#pragma unroll
        for (int q = 0; q < 8; q++) {
            uint32_t a0 = H2[4 * q],     a1 = H2[4 * q + 1];
            uint32_t a2 = H2[4 * q + 2], a3 = H2[4 * q + 3];
#pragma unroll
            for (int ntl = 0; ntl < 8; ntl++) {
                int n = ntl * 8 + g;
                uint32_t b0 = W3s[n * 68 + 8 * q + tig];
                uint32_t b1 = W3s[n * 68 + 8 * q + 4 + tig];
                mma_bf16(acc[ntl], a0, a1, a2, a3, b0, b1);
            }
        }
#pragma unroll
        for (int nt = 0; nt < 8; nt++) {
            int c0 = 8 * nt + 2 * tig;
            float v00 = fmaxf(acc[nt][0] + sB3[c0], 0.f);
            float v01 = fmaxf(acc[nt][1] + sB3[c0 + 1], 0.f);
            float v10 = fmaxf(acc[nt][2] + sB3[c0], 0.f);
            float v11 = fmaxf(acc[nt][3] + sB3[c0 + 1], 0.f);
            int q2 = nt >> 1, off = (nt & 1) * 2;
            H3[4 * q2 + off]     = pack_bf16(v00, v01);
            H3[4 * q2 + off + 1] = pack_bf16(v10, v11);
        }
    }

    {
        float acc[4][4];
#pragma unroll
        for (int ntl = 0; ntl < 4; ntl++)
#pragma unroll
            for (int q = 0; q < 4; q++) acc[ntl][q] = 0.f;
#pragma unroll
        for (int q = 0; q < 4; q++) {
            uint32_t a0 = H3[4 * q],     a1 = H3[4 * q + 1];
            uint32_t a2 = H3[4 * q + 2], a3 = H3[4 * q + 3];
#pragma unroll
            for (int ntl = 0; ntl < 4; ntl++) {
                int n = ntl * 8 + g;
                uint32_t b0 = W4s[n * 36 + 8 * q + tig];
                uint32_t b1 = W4s[n * 36 + 8 * q + 4 + tig];
                mma_bf16(acc[ntl], a0, a1, a2, a3, b0, b1);
            }
        }
        float p0 = 0.f, p1 = 0.f;
#pragma unroll
        for (int nt = 0; nt < 4; nt++) {
            int c0 = 8 * nt + 2 * tig;
            p0 += fmaxf(acc[nt][0] + sB4[c0], 0.f) * sW5[c0]
                + fmaxf(acc[nt][1] + sB4[c0 + 1], 0.f) * sW5[c0 + 1];
            p1 += fmaxf(acc[nt][2] + sB4[c0], 0.f) * sW5[c0]
                + fmaxf(acc[nt][3] + sB4[c0 + 1], 0.f) * sW5[c0 + 1];
        }
#pragma unroll
        for (int o = 1; o <= 2; o <<= 1) {
            p0 += __shfl_xor_sync(0xffffffffu, p0, o);
            p1 += __shfl_xor_sync(0xffffffffu, p1, o);
        }
        if (tig == 0) {
            float bb = sB5[0];
            out[i * 768 + jr0] = (jr0 == i) ? -1000000000.0f : p0 + bb;
            out[i * 768 + jr1] = (jr1 == i) ? -1000000000.0f : p1 + bb;
        }
    }
}

// ---------------- host launch ------------------------------------------------
extern "C" void kernel_launch(void* const* d_in, const int* in_sizes, int n_in,
                              void* d_out, int out_size)
{
    (void)in_sizes; (void)n_in; (void)out_size;
    const float* features = (const float*)d_in[0];
    const float* boxes    = (const float*)d_in[1];
    const float* in_w     = (const float*)d_in[2];
    const float* in_b     = (const float*)d_in[3];
    const float* out_w    = (const float*)d_in[4];
    const float* out_b    = (const float*)d_in[5];
    const float* w1       = (const float*)d_in[6];
    const float* b1       = (const float*)d_in[7];
    const float* lng      = (const float*)d_in[8];
    const float* lnb      = (const float*)d_in[9];
    const float* w2       = (const float*)d_in[10];
    const float* b2       = (const float*)d_in[11];
    const float* w3       = (const float*)d_in[12];
    const float* b3       = (const float*)d_in[13];
    const float* w4       = (const float*)d_in[14];
    const float* b4       = (const float*)d_in[15];
    const float* w5       = (const float*)d_in[16];
    const float* b5       = (const float*)d_in[17];
    float* out = (float*)d_out;

    void *featbf, *inwbf, *outwT, *w1ab, *w1cbf, *w2bf, *w3bf, *w4bf;
    void *qkvbf, *vtbf, *obf, *attbf, *bpbf, *bigB, *bigbias;
    float* Apb;
    cudaGetSymbolAddress(&featbf, g_feat_bf);
    cudaGetSymbolAddress(&inwbf,  g_inw_bf);
    cudaGetSymbolAddress(&outwT,  g_outwT_bf);
    cudaGetSymbolAddress(&w1ab,   g_w1ab_bf);
    cudaGetSymbolAddress(&w1cbf,  g_w1c_bf);
    cudaGetSymbolAddress(&w2bf,   g_w2_bf);
    cudaGetSymbolAddress(&w3bf,   g_w3_bf);
    cudaGetSymbolAddress(&w4bf,   g_w4_bf);
    cudaGetSymbolAddress(&qkvbf,  g_qkv_bf);
    cudaGetSymbolAddress(&vtbf,   g_vT_bf);
    cudaGetSymbolAddress(&obf,    g_o_bf);
    cudaGetSymbolAddress(&attbf,  g_att_bf);
    cudaGetSymbolAddress(&bpbf,   g_Bp_bf);
    cudaGetSymbolAddress(&bigB,   g_bigB_bf);
    cudaGetSymbolAddress(&bigbias, g_bigbias);
    cudaGetSymbolAddress((void**)&Apb, g_Ap);

    cudaFuncSetAttribute(gemm_k256,
                         cudaFuncAttributeMaxDynamicSharedMemorySize, GEMM_SMEM_BYTES);
    cudaFuncSetAttribute(fused_pairs_reg,
                         cudaFuncAttributeMaxDynamicSharedMemorySize, SMEM_BYTES);

    // 1. conversions + transposes + fused bias prep
    convert_pre<<<768, 256>>>(features, in_w, out_w, out_b, w1, b1, w2, w3, w4);

    // 2. Mab = [w1a;w1b] @ out_w  (rows 256-767 of bigB)
    gemm_k256<<<dim3(2, 4), 256, GEMM_SMEM_BYTES>>>(
        (const uint4*)w1ab, (const uint4*)outwT, nullptr, 256, 0,
        (uint32_t*)((char*)bigB + 512 * 256), nullptr, nullptr, nullptr);

    // 3. qkv = feat @ in_w^T + in_b  (+ fused V-transpose scatter)
    gemm_k256<<<dim3(6, 6), 256, GEMM_SMEM_BYTES>>>(
        (const uint4*)featbf, (const uint4*)inwbf, in_b, 768, 1,
        (uint32_t*)qkvbf, nullptr, nullptr, (__nv_bfloat16*)vtbf);

    // 4. flash attention -> o_bf
    attn_flash<<<dim3(6, 8), 256>>>();

    // 5. merged: [att | Ap | Bp] = o @ [out_w | Ma | Mb]^T + bigbias
    gemm_k256<<<dim3(6, 6), 256, GEMM_SMEM_BYTES>>>(
        (const uint4*)obf, (const uint4*)bigB, (const float*)bigbias, 768, 2,
        (uint32_t*)attbf, Apb, (uint32_t*)bpbf, nullptr);

    // 6. fused all-pairs MLP
    fused_pairs_reg<<<dim3(6, 768), 256, SMEM_BYTES>>>(
        boxes, w1, Apb,
        (const uint32_t*)attbf, (const uint32_t*)bpbf,
        (const uint4*)w1cbf, (const uint4*)w2bf,
        (const uint4*)w3bf, (const uint4*)w4bf,
        lng, lnb, b2, b3, b4, w5, b5, out);
}

// round 11
// speedup vs baseline: 1.2212x; 1.0729x over previous
#include <cuda_runtime.h>
#include <cuda_bf16.h>
#include <cstdint>
#include <math.h>

#define NTOK 768
#define DMODEL 256
#define NHEAD 8

// ---------------- scratch (device globals; no allocations allowed) ----------
__device__ __nv_bfloat16 g_feat_bf[NTOK * DMODEL];
__device__ __nv_bfloat16 g_inw_bf[768 * 256];
__device__ __nv_bfloat16 g_outw_bf[256 * 256];
__device__ __nv_bfloat16 g_w1a_bf[256 * 256];
__device__ __nv_bfloat16 g_w1b_bf[256 * 256];
__device__ __nv_bfloat16 g_w1c_bf[256 * 256];
__device__ __nv_bfloat16 g_w2_bf[128 * 256];
__device__ __nv_bfloat16 g_w3_bf[64 * 128];
__device__ __nv_bfloat16 g_w4_bf[32 * 64];
__device__ __nv_bfloat16 g_qkv_bf[NTOK * 768];
__device__ __nv_bfloat16 g_vT_bf[NHEAD * 32 * NTOK];
__device__ __nv_bfloat16 g_o_bf[NTOK * DMODEL];
__device__ __nv_bfloat16 g_att_bf[NTOK * DMODEL];
__device__ __nv_bfloat16 g_Bp_bf[NTOK * DMODEL];
__device__ float g_Ap[NTOK * DMODEL];

// ---------------- helpers ----------------------------------------------------
__device__ __forceinline__ void mma_bf16(float* c, unsigned a0, unsigned a1,
                                         unsigned a2, unsigned a3,
                                         unsigned b0, unsigned b1)
{
    asm volatile(
        "mma.sync.aligned.m16n8k16.row.col.f32.bf16.bf16.f32 "
        "{%0,%1,%2,%3}, {%4,%5,%6,%7}, {%8,%9}, {%0,%1,%2,%3};"
        : "+f"(c[0]), "+f"(c[1]), "+f"(c[2]), "+f"(c[3])
        : "r"(a0), "r"(a1), "r"(a2), "r"(a3), "r"(b0), "r"(b1));
}
__device__ __forceinline__ unsigned pack_bf16(float a, float b)
{
    __nv_bfloat162 h;
    h.x = __float2bfloat16_rn(a);
    h.y = __float2bfloat16_rn(b);
    return *reinterpret_cast<unsigned*>(&h);
}
__device__ __forceinline__ float2 unpack_bf16(unsigned u)
{
    __nv_bfloat162 h = *reinterpret_cast<__nv_bfloat162*>(&u);
    return make_float2(__bfloat162float(h.x), __bfloat162float(h.y));
}
__device__ __forceinline__ float fexp2(float x)
{
    float y;
    asm("ex2.approx.ftz.f32 %0, %1;" : "=f"(y) : "f"(x));
    return y;
}

// ---------------- conversions (R6) -------------------------------------------
__global__ void convert_pre(const float* __restrict__ features,
                            const float* __restrict__ in_w,
                            const float* __restrict__ out_w,
                            const float* __restrict__ w1,
                            const float* __restrict__ w2,
                            const float* __restrict__ w3,
                            const float* __restrict__ w4)
{
    int t = blockIdx.x * 256 + threadIdx.x;
    if (t < 196608) {
        g_feat_bf[t] = __float2bfloat16_rn(features[t]);
        g_inw_bf[t]  = __float2bfloat16_rn(in_w[t]);
    }
    if (t < 65536) {
        int n = t >> 8, d = t & 255;
        g_outw_bf[t] = __float2bfloat16_rn(out_w[t]);
        g_w1a_bf[t]  = __float2bfloat16_rn(w1[n * 771 + d]);
        g_w1b_bf[t]  = __float2bfloat16_rn(w1[n * 771 + 256 + d]);
        g_w1c_bf[t]  = __float2bfloat16_rn(w1[n * 771 + 512 + d]);
    }
    if (t < 32768) g_w2_bf[t] = __float2bfloat16_rn(w2[t]);
    if (t < 8192)  g_w3_bf[t] = __float2bfloat16_rn(w3[t]);
    if (t < 2048)  g_w4_bf[t] = __float2bfloat16_rn(w4[t]);
}

__global__ void build_vT()
{
    int row = blockIdx.x;
    for (int m = threadIdx.x; m < NTOK; m += 256)
        g_vT_bf[row * NTOK + m] = g_qkv_bf[m * 768 + 512 + row];
}

// ---------------- bf16 GEMM, K=256, 128x128 tile, 256 threads (R6) -----------
#define GEMM_SMEM_U32 33792
#define GEMM_SMEM_BYTES (GEMM_SMEM_U32 * 4)

__global__ __launch_bounds__(256, 1) void gemm_bf256(
    const uint4* __restrict__ A4, const uint4* __restrict__ B4,
    const float* __restrict__ bias,
    float* __restrict__ Cf, uint32_t* __restrict__ Cb, int N)
{
    extern __shared__ uint32_t sg[];
    uint32_t* As = sg;
    uint32_t* Bs = sg + 16896;

    const int m0 = blockIdx.y * 128;
    const int n0 = blockIdx.x * 128;
    const int t  = threadIdx.x;
    const int w  = t >> 5;
    const int lane = t & 31;
    const int g   = lane >> 2;
    const int tig = lane & 3;
    const int r0i = w * 16 + g, r1i = r0i + 8;

    for (int idx = t; idx < 4096; idx += 256) {
        int r = idx >> 5, c4 = idx & 31;
        *(uint4*)&As[r * 132 + c4 * 4] = A4[(m0 + r) * 32 + c4];
        *(uint4*)&Bs[r * 132 + c4 * 4] = B4[(n0 + r) * 32 + c4];
    }
    __syncthreads();

    float acc[16][4];
#pragma unroll
    for (int nt = 0; nt < 16; nt++)
#pragma unroll
        for (int q = 0; q < 4; q++) acc[nt][q] = 0.f;

#pragma unroll
    for (int q = 0; q < 16; q++) {
        uint32_t a0 = As[r0i * 132 + 8 * q + tig];
        uint32_t a1 = As[r1i * 132 + 8 * q + tig];
        uint32_t a2 = As[r0i * 132 + 8 * q + 4 + tig];
        uint32_t a3 = As[r1i * 132 + 8 * q + 4 + tig];
#pragma unroll
        for (int nt = 0; nt < 16; nt++) {
            int n = 8 * nt + g;
            uint32_t b0 = Bs[n * 132 + 8 * q + tig];
            uint32_t b1 = Bs[n * 132 + 8 * q + 4 + tig];
            mma_bf16(acc[nt], a0, a1, a2, a3, b0, b1);
        }
    }

    const int gm0 = m0 + r0i, gm1 = m0 + r1i;
#pragma unroll
    for (int nt = 0; nt < 16; nt++) {
        int gn = n0 + 8 * nt + 2 * tig;
        float bi0 = bias ? bias[gn] : 0.f;
        float bi1 = bias ? bias[gn + 1] : 0.f;
        float v00 = acc[nt][0] + bi0, v01 = acc[nt][1] + bi1;
        float v10 = acc[nt][2] + bi0, v11 = acc[nt][3] + bi1;
        if (Cf) {
            *(float2*)&Cf[(size_t)gm0 * N + gn] = make_float2(v00, v01);
            *(float2*)&Cf[(size_t)gm1 * N + gn] = make_float2(v10, v11);
        }
        if (Cb) {
            Cb[gm0 * (N >> 1) + (gn >> 1)] = pack_bf16(v00, v01);
            Cb[gm1 * (N >> 1) + (gn >> 1)] = pack_bf16(v10, v11);
        }
    }
}

// ---------------- flash attention (R6: 128-row q tiles, 256 thr) -------------
__global__ __launch_bounds__(256, 1) void attn_flash()
{
    __shared__ uint32_t Ks[128 * 20];
    __shared__ uint32_t VTs[32 * 68];

    const int q0 = blockIdx.x * 128;
    const int h  = blockIdx.y;
    const int t  = threadIdx.x;
    const int w  = t >> 5;
    const int lane = t & 31;
    const int g   = lane >> 2;
    const int tig = lane & 3;
    const int r0i = w * 16 + g, r1i = r0i + 8;

    const uint32_t* qkvU = (const uint32_t*)g_qkv_bf;
    const uint32_t* vtU  = (const uint32_t*)g_vT_bf;

    const float CS = 1.4426950408889634f * 0.17677669529663687f;

    uint32_t qf[8];
#pragma unroll
    for (int qq = 0; qq < 2; qq++) {
        qf[4 * qq]     = qkvU[(q0 + r0i) * 384 + h * 16 + 8 * qq + tig];
        qf[4 * qq + 1] = qkvU[(q0 + r1i) * 384 + h * 16 + 8 * qq + tig];
        qf[4 * qq + 2] = qkvU[(q0 + r0i) * 384 + h * 16 + 8 * qq + 4 + tig];
        qf[4 * qq + 3] = qkvU[(q0 + r1i) * 384 + h * 16 + 8 * qq + 4 + tig];
    }

    float acc_o[4][4];
#pragma unroll
    for (int nt = 0; nt < 4; nt++)
#pragma unroll
        for (int e = 0; e < 4; e++) acc_o[nt][e] = 0.f;
    float m0s = -1e30f, m1s = -1e30f, l0p = 0.f, l1p = 0.f;

    for (int kt = 0; kt < 6; kt++) {
        __syncthreads();
        for (int idx = t; idx < 2048; idx += 256) {
            int r = idx >> 4, c = idx & 15;
            Ks[r * 20 + c] = qkvU[(kt * 128 + r) * 384 + 128 + h * 16 + c];
        }
        for (int idx = t; idx < 2048; idx += 256) {
            int d = idx >> 6, c = idx & 63;
            VTs[d * 68 + c] = vtU[(h * 32 + d) * 384 + kt * 64 + c];
        }
        __syncthreads();

        float accs[16][4];
#pragma unroll
        for (int nt = 0; nt < 16; nt++)
#pragma unroll
            for (int e = 0; e < 4; e++) accs[nt][e] = 0.f;
#pragma unroll
        for (int qq = 0; qq < 2; qq++) {
            uint32_t a0 = qf[4 * qq], a1 = qf[4 * qq + 1];
            uint32_t a2 = qf[4 * qq + 2], a3 = qf[4 * qq + 3];
#pragma unroll
            for (int nt = 0; nt < 16; nt++) {
                int n = 8 * nt + g;
                uint32_t b0 = Ks[n * 20 + 8 * qq + tig];
                uint32_t b1 = Ks[n * 20 + 8 * qq + 4 + tig];
                mma_bf16(accs[nt], a0, a1, a2, a3, b0, b1);
            }
        }
        float lm0 = -1e30f, lm1 = -1e30f;
#pragma unroll
        for (int nt = 0; nt < 16; nt++) {
            accs[nt][0] *= CS; accs[nt][1] *= CS;
            accs[nt][2] *= CS; accs[nt][3] *= CS;
            lm0 = fmaxf(lm0, fmaxf(accs[nt][0], accs[nt][1]));
            lm1 = fmaxf(lm1, fmaxf(accs[nt][2], accs[nt][3]));
        }
#pragma unroll
        for (int o = 1; o <= 2; o <<= 1) {
            lm0 = fmaxf(lm0, __shfl_xor_sync(0xffffffffu, lm0, o));
            lm1 = fmaxf(lm1, __shfl_xor_sync(0xffffffffu, lm1, o));
        }
        float mn0 = fmaxf(m0s, lm0), mn1 = fmaxf(m1s, lm1);
        float al0 = fexp2(m0s - mn0), al1 = fexp2(m1s - mn1);
        m0s = mn0; m1s = mn1;

        float ps0 = 0.f, ps1 = 0.f;
        uint32_t Pf[32];
#pragma unroll
        for (int nt = 0; nt < 16; nt++) {
            float p00 = fexp2(accs[nt][0] - mn0);
            float p01 = fexp2(accs[nt][1] - mn0);
            float p10 = fexp2(accs[nt][2] - mn1);
            float p11 = fexp2(accs[nt][3] - mn1);
            ps0 += p00 + p01; ps1 += p10 + p11;
            int q2 = nt >> 1, off = (nt & 1) * 2;
            Pf[4 * q2 + off]     = pack_bf16(p00, p01);
            Pf[4 * q2 + off + 1] = pack_bf16(p10, p11);
        }
        l0p = l0p * al0 + ps0;
        l1p = l1p * al1 + ps1;
#pragma unroll
        for (int nt = 0; nt < 4; nt++) {
            acc_o[nt][0] *= al0; acc_o[nt][1] *= al0;
            acc_o[nt][2] *= al1; acc_o[nt][3] *= al1;
        }
#pragma unroll
        for (int q = 0; q < 8; q++) {
            uint32_t a0 = Pf[4 * q], a1 = Pf[4 * q + 1];
            uint32_t a2 = Pf[4 * q + 2], a3 = Pf[4 * q + 3];
#pragma unroll
            for (int nt = 0; nt < 4; nt++) {
                int n = 8 * nt + g;
                uint32_t b0 = VTs[n * 68 + 8 * q + tig];
                uint32_t b1 = VTs[n * 68 + 8 * q + 4 + tig];
                mma_bf16(acc_o[nt], a0, a1, a2, a3, b0, b1);
            }
        }
    }

#pragma unroll
    for (int o = 1; o <= 2; o <<= 1) {
        l0p += __shfl_xor_sync(0xffffffffu, l0p, o);
        l1p += __shfl_xor_sync(0xffffffffu, l1p, o);
    }
    float inv0 = 1.f / l0p, inv1 = 1.f / l1p;
    uint32_t* oU = (uint32_t*)g_o_bf;
#pragma unroll
    for (int nt = 0; nt < 4; nt++) {
        oU[(q0 + r0i) * 128 + h * 16 + 4 * nt + tig] =
            pack_bf16(acc_o[nt][0] * inv0, acc_o[nt][1] * inv0);
        oU[(q0 + r1i) * 128 + h * 16 + 4 * nt + tig] =
            pack_bf16(acc_o[nt][2] * inv1, acc_o[nt][3] * inv1);
    }
}

// ---------------- fused all-pairs MLP: 384 threads, 192-j tiles --------------
#define OFF_W1   0
#define OFF_W2   33792
#define OFF_W3   50688
#define OFF_W4   55040
#define OFF_PACK 56192
#define OFF_LGB  57216
#define OFF_B2   57728
#define OFF_B3   57856
#define OFF_B4   57920
#define OFF_W5   57952
#define OFF_B5   57984
#define SMEM_U32 57988
#define SMEM_BYTES (SMEM_U32 * 4)

__global__ __launch_bounds__(384, 1) void fused_pairs_reg(
    const float* __restrict__ boxes,
    const float* __restrict__ w1,
    const float* __restrict__ Ap,
    const uint32_t* __restrict__ attbf,
    const uint32_t* __restrict__ bpbf,
    const uint4* __restrict__ w1v, const uint4* __restrict__ w2v,
    const uint4* __restrict__ w3v, const uint4* __restrict__ w4v,
    const float* __restrict__ lng, const float* __restrict__ lnb,
    const float* __restrict__ b2, const float* __restrict__ b3,
    const float* __restrict__ b4,
    const float* __restrict__ w5, const float* __restrict__ b5,
    float* __restrict__ out)
{
    extern __shared__ uint32_t sm[];
    uint32_t* W1s = sm + OFF_W1;
    uint32_t* W2s = sm + OFF_W2;
    uint32_t* W3s = sm + OFF_W3;
    uint32_t* W4s = sm + OFF_W4;
    float4*   sPack = (float4*)(sm + OFF_PACK);
    float2*   sLgb  = (float2*)(sm + OFF_LGB);
    float*    sB2   = (float*)(sm + OFF_B2);
    float*    sB3   = (float*)(sm + OFF_B3);
    float*    sB4   = (float*)(sm + OFF_B4);
    float*    sW5   = (float*)(sm + OFF_W5);
    float*    sB5   = (float*)(sm + OFF_B5);

    const int i  = blockIdx.y;
    const int j0 = blockIdx.x * 192;
    const int t  = threadIdx.x;
    const int w  = t >> 5;
    const int lane = t & 31;
    const int g   = lane >> 2;
    const int tig = lane & 3;

    for (int idx = t; idx < 8192; idx += 384) {
        int r = idx >> 5, c4 = idx & 31;
        *(uint4*)&W1s[r * 132 + c4 * 4] = w1v[idx];
    }
    for (int idx = t; idx < 4096; idx += 384) {
        int r = idx >> 5, c4 = idx & 31;
        *(uint4*)&W2s[r * 132 + c4 * 4] = w2v[idx];
    }
    for (int idx = t; idx < 1024; idx += 384) {
        int r = idx >> 4, c4 = idx & 15;
        *(uint4*)&W3s[r * 68 + c4 * 4] = w3v[idx];
    }
    for (int idx = t; idx < 256; idx += 384) {
        int r = idx >> 3, c4 = idx & 7;
        *(uint4*)&W4s[r * 36 + c4 * 4] = w4v[idx];
    }
    if (t < 256) {
        int k = t;
        sPack[k] = make_float4(Ap[i * 256 + k], w1[k * 771 + 768],
                               w1[k * 771 + 769], w1[k * 771 + 770]);
        sLgb[k]  = make_float2(lng[k], lnb[k]);
        if (k < 128) sB2[k] = b2[k];
        if (k < 64)  sB3[k] = b3[k];
        if (k < 32)  { sB4[k] = b4[k]; sW5[k] = w5[k]; }
        if (k == 0)  sB5[0] = b5[0];
    }
    __syncthreads();

    const int r0 = w * 16 + g, r1 = r0 + 8;
    const int jr0 = j0 + r0, jr1 = j0 + r1;

    float bxi = boxes[i * 4], byi = boxes[i * 4 + 1];
    float dy0 = byi - boxes[jr0 * 4 + 1];
    float dy1 = byi - boxes[jr1 * 4 + 1];
    float sx0 = fabsf(bxi - boxes[jr0 * 4]), sya0 = fabsf(dy0), sys0 = dy0;
    float sx1 = fabsf(bxi - boxes[jr1 * 4]), sya1 = fabsf(dy1), sys1 = dy1;

    uint32_t A1[64];
#pragma unroll
    for (int q = 0; q < 16; q++) {
        int p0 = 8 * q + tig, p1 = p0 + 4;
        float2 ai0 = unpack_bf16(attbf[i * 128 + p0]);
        float2 ai1 = unpack_bf16(attbf[i * 128 + p1]);
        float2 j00 = unpack_bf16(attbf[jr0 * 128 + p0]);
        float2 j10 = unpack_bf16(attbf[jr1 * 128 + p0]);
        float2 j01 = unpack_bf16(attbf[jr0 * 128 + p1]);
        float2 j11 = unpack_bf16(attbf[jr1 * 128 + p1]);
        A1[4 * q]     = pack_bf16(j00.x * ai0.x, j00.y * ai0.y);
        A1[4 * q + 1] = pack_bf16(j10.x * ai0.x, j10.y * ai0.y);
        A1[4 * q + 2] = pack_bf16(j01.x * ai1.x, j01.y * ai1.y);
        A1[4 * q + 3] = pack_bf16(j11.x * ai1.x, j11.y * ai1.y);
    }

    uint32_t H1[64];
    float sum0 = 0.f, sq0 = 0.f, sum1 = 0.f, sq1 = 0.f;
#pragma unroll
    for (int h = 0; h < 2; h++) {
        float acc[16][4];
#pragma unroll
        for (int ntl = 0; ntl < 16; ntl++)
#pragma unroll
            for (int q = 0; q < 4; q++) acc[ntl][q] = 0.f;

#pragma unroll
        for (int q = 0; q < 16; q++) {
            uint32_t a0 = A1[4 * q],     a1 = A1[4 * q + 1];
            uint32_t a2 = A1[4 * q + 2], a3 = A1[4 * q + 3];
#pragma unroll
            for (int ntl = 0; ntl < 16; ntl++) {
                int n = (h * 16 + ntl) * 8 + g;
                uint32_t b0 = W1s[n * 132 + 8 * q + tig];
                uint32_t b1 = W1s[n * 132 + 8 * q + 4 + tig];
                mma_bf16(acc[ntl], a0, a1, a2, a3, b0, b1);
            }
        }
#pragma unroll
        for (int ntl = 0; ntl < 16; ntl++) {
            int nt = h * 16 + ntl;
            int c0 = 8 * nt + 2 * tig;
            float4 p0 = sPack[c0], p1 = sPack[c0 + 1];
            float2 bp0 = unpack_bf16(bpbf[jr0 * 128 + 4 * nt + tig]);
            float2 bp1 = unpack_bf16(bpbf[jr1 * 128 + 4 * nt + tig]);
            float v00 = acc[ntl][0] + p0.x + sx0 * p0.y + sya0 * p0.z + sys0 * p0.w + bp0.x;
            float v01 = acc[ntl][1] + p1.x + sx0 * p1.y + sya0 * p1.z + sys0 * p1.w + bp0.y;
            float v10 = acc[ntl][2] + p0.x + sx1 * p0.y + sya1 * p0.z + sys1 * p0.w + bp1.x;
            float v11 = acc[ntl][3] + p1.x + sx1 * p1.y + sya1 * p1.z + sys1 * p1.w + bp1.y;
            v00 = fmaxf(v00, 0.f); v01 = fmaxf(v01, 0.f);
            v10 = fmaxf(v10, 0.f); v11 = fmaxf(v11, 0.f);
            sum0 += v00 + v01; sq0 += v00 * v00 + v01 * v01;
            sum1 += v10 + v11; sq1 += v10 * v10 + v11 * v11;
            int q2 = nt >> 1, off = (nt & 1) * 2;
            H1[4 * q2 + off]     = pack_bf16(v00, v01);
            H1[4 * q2 + off + 1] = pack_bf16(v10, v11);
        }
    }

#pragma unroll
    for (int o = 1; o <= 2; o <<= 1) {
        sum0 += __shfl_xor_sync(0xffffffffu, sum0, o);
        sq0  += __shfl_xor_sync(0xffffffffu, sq0,  o);
        sum1 += __shfl_xor_sync(0xffffffffu, sum1, o);
        sq1  += __shfl_xor_sync(0xffffffffu, sq1,  o);
    }
    float mu0 = sum0 * (1.f / 256.f);
    float rs0 = rsqrtf(sq0 * (1.f / 256.f) - mu0 * mu0 + 1e-5f);
    float mu1 = sum1 * (1.f / 256.f);
    float rs1 = rsqrtf(sq1 * (1.f / 256.f) - mu1 * mu1 + 1e-5f);
#pragma unroll
    for (int q = 0; q < 16; q++) {
#pragma unroll
        for (int e2 = 0; e2 < 2; e2++) {
            int col = 16 * q + 8 * e2 + 2 * tig;
            float2 gb0 = sLgb[col], gb1 = sLgb[col + 1];
#pragma unroll
            for (int e = 0; e < 2; e++) {
                int idx = 4 * q + 2 * e2 + e;
                float2 v = unpack_bf16(H1[idx]);
                float m = e ? mu1 : mu0, rr = e ? rs1 : rs0;
                H1[idx] = pack_bf16((v.x - m) * rr * gb0.x + gb0.y,
                                    (v.y - m) * rr * gb1.x + gb1.y);
            }
        }
    }

    uint32_t H2[32];
#pragma unroll
    for (int h = 0; h < 2; h++) {
        float acc[8][4];
#pragma unroll
        for (int ntl = 0; ntl < 8; ntl++)
#pragma unroll
            for (int q = 0; q < 4; q++) acc[ntl][q] = 0.f;
#pragma unroll
        for (int q = 0; q < 16; q++) {
            uint32_t a0 = H1[4 * q],     a1 = H1[4 * q + 1];
            uint32_t a2 = H1[4 * q + 2], a3 = H1[4 * q + 3];
#pragma unroll
            for (int ntl = 0; ntl < 8; ntl++) {
                int n = (h * 8 + ntl) * 8 + g;
                uint32_t b0 = W2s[n * 132 + 8 * q + tig];
                uint32_t b1 = W2s[n * 132 + 8 * q + 4 + tig];
                mma_bf16(acc[ntl], a0, a1, a2, a3, b0, b1);
            }
        }
#pragma unroll
        for (int ntl = 0; ntl < 8; ntl++) {
            int nt = h * 8 + ntl;
            int c0 = 8 * nt + 2 * tig;
            float v00 = fmaxf(acc[ntl][0] + sB2[c0], 0.f);
            float v01 = fmaxf(acc[ntl][1] + sB2[c0 + 1], 0.f);
            float v10 = fmaxf(acc[ntl][2] + sB2[c0], 0.f);
            float v11 = fmaxf(acc[ntl][3] + sB2[c0 + 1], 0.f);
            int q2 = nt >> 1, off = (nt & 1) * 2;
            H2[4 * q2 + off]     = pack_bf16(v00, v01);
            H2[4 * q2 + off + 1] = pack_bf16(v10, v11);
        }
    }

    uint32_t H3[16];
    {
        float acc[8][4];
#pragma unroll
        for (int ntl = 0; ntl < 8; ntl++)
#pragma unroll
            for (int q = 0; q < 4; q++) acc[ntl][q] = 0.f;
#pragma unroll
        for (int q = 0; q < 8; q++) {
            uint32_t a0 = H2[4 * q],     a1 = H2[4 * q + 1];
            uint32_t a2 = H2[4 * q + 2], a3 = H2[4 * q + 3];
#pragma unroll
            for (int ntl = 0; ntl < 8; ntl++) {
                int n = ntl * 8 + g;
                uint32_t b0 = W3s[n * 68 + 8 * q + tig];
                uint32_t b1 = W3s[n * 68 + 8 * q + 4 + tig];
                mma_bf16(acc[ntl], a0, a1, a2, a3, b0, b1);
            }
        }
#pragma unroll
        for (int nt = 0; nt < 8; nt++) {
            int c0 = 8 * nt + 2 * tig;
            float v00 = fmaxf(acc[nt][0] + sB3[c0], 0.f);
            float v01 = fmaxf(acc[nt][1] + sB3[c0 + 1], 0.f);
            float v10 = fmaxf(acc[nt][2] + sB3[c0], 0.f);
            float v11 = fmaxf(acc[nt][3] + sB3[c0 + 1], 0.f);
            int q2 = nt >> 1, off = (nt & 1) * 2;
            H3[4 * q2 + off]     = pack_bf16(v00, v01);
            H3[4 * q2 + off + 1] = pack_bf16(v10, v11);
        }
    }

    {
        float acc[4][4];
#pragma unroll
        for (int ntl = 0; ntl < 4; ntl++)
#pragma unroll
            for (int q = 0; q < 4; q++) acc[ntl][q] = 0.f;
#pragma unroll
        for (int q = 0; q < 4; q++) {
            uint32_t a0 = H3[4 * q],     a1 = H3[4 * q + 1];
            uint32_t a2 = H3[4 * q + 2], a3 = H3[4 * q + 3];
#pragma unroll
            for (int ntl = 0; ntl < 4; ntl++) {
                int n = ntl * 8 + g;
                uint32_t b0 = W4s[n * 36 + 8 * q + tig];
                uint32_t b1 = W4s[n * 36 + 8 * q + 4 + tig];
                mma_bf16(acc[ntl], a0, a1, a2, a3, b0, b1);
            }
        }
        float p0 = 0.f, p1 = 0.f;
#pragma unroll
        for (int nt = 0; nt < 4; nt++) {
            int c0 = 8 * nt + 2 * tig;
            p0 += fmaxf(acc[nt][0] + sB4[c0], 0.f) * sW5[c0]
                + fmaxf(acc[nt][1] + sB4[c0 + 1], 0.f) * sW5[c0 + 1];
            p1 += fmaxf(acc[nt][2] + sB4[c0], 0.f) * sW5[c0]
                + fmaxf(acc[nt][3] + sB4[c0 + 1], 0.f) * sW5[c0 + 1];
        }
#pragma unroll
        for (int o = 1; o <= 2; o <<= 1) {
            p0 += __shfl_xor_sync(0xffffffffu, p0, o);
            p1 += __shfl_xor_sync(0xffffffffu, p1, o);
        }
        if (tig == 0) {
            float bb = sB5[0];
            out[i * 768 + jr0] = (jr0 == i) ? -1000000000.0f : p0 + bb;
            out[i * 768 + jr1] = (jr1 == i) ? -1000000000.0f : p1 + bb;
        }
    }
}

// ---------------- host launch ------------------------------------------------
extern "C" void kernel_launch(void* const* d_in, const int* in_sizes, int n_in,
                              void* d_out, int out_size)
{
    (void)in_sizes; (void)n_in; (void)out_size;
    const float* features = (const float*)d_in[0];
    const float* boxes    = (const float*)d_in[1];
    const float* in_w     = (const float*)d_in[2];
    const float* in_b     = (const float*)d_in[3];
    const float* out_w    = (const float*)d_in[4];
    const float* out_b    = (const float*)d_in[5];
    const float* w1       = (const float*)d_in[6];
    const float* b1       = (const float*)d_in[7];
    const float* lng      = (const float*)d_in[8];
    const float* lnb      = (const float*)d_in[9];
    const float* w2       = (const float*)d_in[10];
    const float* b2       = (const float*)d_in[11];
    const float* w3       = (const float*)d_in[12];
    const float* b3       = (const float*)d_in[13];
    const float* w4       = (const float*)d_in[14];
    const float* b4       = (const float*)d_in[15];
    const float* w5       = (const float*)d_in[16];
    const float* b5       = (const float*)d_in[17];
    float* out = (float*)d_out;

    void *featbf, *inwbf, *outwbf, *w1abf, *w1bbf, *w1cbf, *w2bf, *w3bf, *w4bf;
    void *qkvbf, *obf, *attbf, *bpbf;
    float* Apb;
    cudaGetSymbolAddress(&featbf, g_feat_bf);
    cudaGetSymbolAddress(&inwbf,  g_inw_bf);
    cudaGetSymbolAddress(&outwbf, g_outw_bf);
    cudaGetSymbolAddress(&w1abf,  g_w1a_bf);
    cudaGetSymbolAddress(&w1bbf,  g_w1b_bf);
    cudaGetSymbolAddress(&w1cbf,  g_w1c_bf);
    cudaGetSymbolAddress(&w2bf,   g_w2_bf);
    cudaGetSymbolAddress(&w3bf,   g_w3_bf);
    cudaGetSymbolAddress(&w4bf,   g_w4_bf);
    cudaGetSymbolAddress(&qkvbf,  g_qkv_bf);
    cudaGetSymbolAddress(&obf,    g_o_bf);
    cudaGetSymbolAddress(&attbf,  g_att_bf);
    cudaGetSymbolAddress(&bpbf,   g_Bp_bf);
    cudaGetSymbolAddress((void**)&Apb, g_Ap);

    cudaFuncSetAttribute(gemm_bf256,
                         cudaFuncAttributeMaxDynamicSharedMemorySize, GEMM_SMEM_BYTES);
    cudaFuncSetAttribute(fused_pairs_reg,
                         cudaFuncAttributeMaxDynamicSharedMemorySize, SMEM_BYTES);

    convert_pre<<<768, 256>>>(features, in_w, out_w, w1, w2, w3, w4);

    gemm_bf256<<<dim3(6, 6), 256, GEMM_SMEM_BYTES>>>(
        (const uint4*)featbf, (const uint4*)inwbf, in_b,
        nullptr, (uint32_t*)qkvbf, 768);

    build_vT<<<256, 256>>>();

    attn_flash<<<dim3(6, 8), 256>>>();

    gemm_bf256<<<dim3(2, 6), 256, GEMM_SMEM_BYTES>>>(
        (const uint4*)obf, (const uint4*)outwbf, out_b,
        nullptr, (uint32_t*)attbf, 256);

    gemm_bf256<<<dim3(2, 6), 256, GEMM_SMEM_BYTES>>>(
        (const uint4*)attbf, (const uint4*)w1abf, b1,
        Apb, nullptr, 256);

    gemm_bf256<<<dim3(2, 6), 256, GEMM_SMEM_BYTES>>>(
        (const uint4*)attbf, (const uint4*)w1bbf, nullptr,
        nullptr, (uint32_t*)bpbf, 256);

    fused_pairs_reg<<<dim3(4, 768), 384, SMEM_BYTES>>>(
        boxes, w1, Apb,
        (const uint32_t*)attbf, (const uint32_t*)bpbf,
        (const uint4*)w1cbf, (const uint4*)w2bf,
        (const uint4*)w3bf, (const uint4*)w4bf,
        lng, lnb, b2, b3, b4, w5, b5, out);
}

// round 13
// speedup vs baseline: 1.3379x; 1.0955x over previous
#include <cuda_runtime.h>
#include <cuda_bf16.h>
#include <cstdint>
#include <math.h>

#define NTOK 768
#define DMODEL 256
#define NHEAD 8

// ---------------- scratch (device globals; no allocations allowed) ----------
__device__ __nv_bfloat16 g_feat_bf[NTOK * DMODEL];
__device__ __nv_bfloat16 g_inw_bf[768 * 256];
__device__ __nv_bfloat16 g_outw_bf[256 * 256];
__device__ __nv_bfloat16 g_w1a_bf[256 * 256];
__device__ __nv_bfloat16 g_w1b_bf[256 * 256];
__device__ __nv_bfloat16 g_w1c_bf[256 * 256];
__device__ __nv_bfloat16 g_w2_bf[128 * 256];
__device__ __nv_bfloat16 g_w3_bf[64 * 128];
__device__ __nv_bfloat16 g_w4_bf[32 * 64];
__device__ __nv_bfloat16 g_qkv_bf[NTOK * 768];
__device__ __nv_bfloat16 g_vT_bf[NHEAD * 32 * NTOK];
__device__ __nv_bfloat16 g_o_bf[NTOK * DMODEL];
__device__ __nv_bfloat16 g_att_bf[NTOK * DMODEL];
__device__ __nv_bfloat16 g_Bp_bf[NTOK * DMODEL];
__device__ float g_Ap[NTOK * DMODEL];

// ---------------- helpers ----------------------------------------------------
__device__ __forceinline__ void mma_bf16(float* c, unsigned a0, unsigned a1,
                                         unsigned a2, unsigned a3,
                                         unsigned b0, unsigned b1)
{
    asm volatile(
        "mma.sync.aligned.m16n8k16.row.col.f32.bf16.bf16.f32 "
        "{%0,%1,%2,%3}, {%4,%5,%6,%7}, {%8,%9}, {%0,%1,%2,%3};"
        : "+f"(c[0]), "+f"(c[1]), "+f"(c[2]), "+f"(c[3])
        : "r"(a0), "r"(a1), "r"(a2), "r"(a3), "r"(b0), "r"(b1));
}
__device__ __forceinline__ unsigned pack_bf16(float a, float b)
{
    __nv_bfloat162 h;
    h.x = __float2bfloat16_rn(a);
    h.y = __float2bfloat16_rn(b);
    return *reinterpret_cast<unsigned*>(&h);
}
__device__ __forceinline__ float2 unpack_bf16(unsigned u)
{
    __nv_bfloat162 h = *reinterpret_cast<__nv_bfloat162*>(&u);
    return make_float2(__bfloat162float(h.x), __bfloat162float(h.y));
}
__device__ __forceinline__ float fexp2(float x)
{
    float y;
    asm("ex2.approx.ftz.f32 %0, %1;" : "=f"(y) : "f"(x));
    return y;
}

// ---------------- conversions (R6) -------------------------------------------
__global__ void convert_pre(const float* __restrict__ features,
                            const float* __restrict__ in_w,
                            const float* __restrict__ out_w,
                            const float* __restrict__ w1,
                            const float* __restrict__ w2,
                            const float* __restrict__ w3,
                            const float* __restrict__ w4)
{
    int t = blockIdx.x * 256 + threadIdx.x;
    if (t < 196608) {
        g_feat_bf[t] = __float2bfloat16_rn(features[t]);
        g_inw_bf[t]  = __float2bfloat16_rn(in_w[t]);
    }
    if (t < 65536) {
        int n = t >> 8, d = t & 255;
        g_outw_bf[t] = __float2bfloat16_rn(out_w[t]);
        g_w1a_bf[t]  = __float2bfloat16_rn(w1[n * 771 + d]);
        g_w1b_bf[t]  = __float2bfloat16_rn(w1[n * 771 + 256 + d]);
        g_w1c_bf[t]  = __float2bfloat16_rn(w1[n * 771 + 512 + d]);
    }
    if (t < 32768) g_w2_bf[t] = __float2bfloat16_rn(w2[t]);
    if (t < 8192)  g_w3_bf[t] = __float2bfloat16_rn(w3[t]);
    if (t < 2048)  g_w4_bf[t] = __float2bfloat16_rn(w4[t]);
}

__global__ void build_vT()
{
    int row = blockIdx.x;
    for (int m = threadIdx.x; m < NTOK; m += 256)
        g_vT_bf[row * NTOK + m] = g_qkv_bf[m * 768 + 512 + row];
}

// ---------------- bf16 GEMM, K=256, 128x128 tile, 256 threads (R6) -----------
#define GEMM_SMEM_U32 33792
#define GEMM_SMEM_BYTES (GEMM_SMEM_U32 * 4)

__global__ __launch_bounds__(256, 1) void gemm_bf256(
    const uint4* __restrict__ A4, const uint4* __restrict__ B4,
    const float* __restrict__ bias,
    float* __restrict__ Cf, uint32_t* __restrict__ Cb, int N)
{
    extern __shared__ uint32_t sg[];
    uint32_t* As = sg;
    uint32_t* Bs = sg + 16896;

    const int m0 = blockIdx.y * 128;
    const int n0 = blockIdx.x * 128;
    const int t  = threadIdx.x;
    const int w  = t >> 5;
    const int lane = t & 31;
    const int g   = lane >> 2;
    const int tig = lane & 3;
    const int r0i = w * 16 + g, r1i = r0i + 8;

    for (int idx = t; idx < 4096; idx += 256) {
        int r = idx >> 5, c4 = idx & 31;
        *(uint4*)&As[r * 132 + c4 * 4] = A4[(m0 + r) * 32 + c4];
        *(uint4*)&Bs[r * 132 + c4 * 4] = B4[(n0 + r) * 32 + c4];
    }
    __syncthreads();

    float acc[16][4];
#pragma unroll
    for (int nt = 0; nt < 16; nt++)
#pragma unroll
        for (int q = 0; q < 4; q++) acc[nt][q] = 0.f;

#pragma unroll
    for (int q = 0; q < 16; q++) {
        uint32_t a0 = As[r0i * 132 + 8 * q + tig];
        uint32_t a1 = As[r1i * 132 + 8 * q + tig];
        uint32_t a2 = As[r0i * 132 + 8 * q + 4 + tig];
        uint32_t a3 = As[r1i * 132 + 8 * q + 4 + tig];
#pragma unroll
        for (int nt = 0; nt < 16; nt++) {
            int n = 8 * nt + g;
            uint32_t b0 = Bs[n * 132 + 8 * q + tig];
            uint32_t b1 = Bs[n * 132 + 8 * q + 4 + tig];
            mma_bf16(acc[nt], a0, a1, a2, a3, b0, b1);
        }
    }

    const int gm0 = m0 + r0i, gm1 = m0 + r1i;
#pragma unroll
    for (int nt = 0; nt < 16; nt++) {
        int gn = n0 + 8 * nt + 2 * tig;
        float bi0 = bias ? bias[gn] : 0.f;
        float bi1 = bias ? bias[gn + 1] : 0.f;
        float v00 = acc[nt][0] + bi0, v01 = acc[nt][1] + bi1;
        float v10 = acc[nt][2] + bi0, v11 = acc[nt][3] + bi1;
        if (Cf) {
            *(float2*)&Cf[(size_t)gm0 * N + gn] = make_float2(v00, v01);
            *(float2*)&Cf[(size_t)gm1 * N + gn] = make_float2(v10, v11);
        }
        if (Cb) {
            Cb[gm0 * (N >> 1) + (gn >> 1)] = pack_bf16(v00, v01);
            Cb[gm1 * (N >> 1) + (gn >> 1)] = pack_bf16(v10, v11);
        }
    }
}

// ---------------- flash attention (R6: 128-row q tiles, 256 thr) -------------
__global__ __launch_bounds__(256, 1) void attn_flash()
{
    __shared__ uint32_t Ks[128 * 20];
    __shared__ uint32_t VTs[32 * 68];

    const int q0 = blockIdx.x * 128;
    const int h  = blockIdx.y;
    const int t  = threadIdx.x;
    const int w  = t >> 5;
    const int lane = t & 31;
    const int g   = lane >> 2;
    const int tig = lane & 3;
    const int r0i = w * 16 + g, r1i = r0i + 8;

    const uint32_t* qkvU = (const uint32_t*)g_qkv_bf;
    const uint32_t* vtU  = (const uint32_t*)g_vT_bf;

    const float CS = 1.4426950408889634f * 0.17677669529663687f;

    uint32_t qf[8];
#pragma unroll
    for (int qq = 0; qq < 2; qq++) {
        qf[4 * qq]     = qkvU[(q0 + r0i) * 384 + h * 16 + 8 * qq + tig];
        qf[4 * qq + 1] = qkvU[(q0 + r1i) * 384 + h * 16 + 8 * qq + tig];
        qf[4 * qq + 2] = qkvU[(q0 + r0i) * 384 + h * 16 + 8 * qq + 4 + tig];
        qf[4 * qq + 3] = qkvU[(q0 + r1i) * 384 + h * 16 + 8 * qq + 4 + tig];
    }

    float acc_o[4][4];
#pragma unroll
    for (int nt = 0; nt < 4; nt++)
#pragma unroll
        for (int e = 0; e < 4; e++) acc_o[nt][e] = 0.f;
    float m0s = -1e30f, m1s = -1e30f, l0p = 0.f, l1p = 0.f;

    for (int kt = 0; kt < 6; kt++) {
        __syncthreads();
        for (int idx = t; idx < 2048; idx += 256) {
            int r = idx >> 4, c = idx & 15;
            Ks[r * 20 + c] = qkvU[(kt * 128 + r) * 384 + 128 + h * 16 + c];
        }
        for (int idx = t; idx < 2048; idx += 256) {
            int d = idx >> 6, c = idx & 63;
            VTs[d * 68 + c] = vtU[(h * 32 + d) * 384 + kt * 64 + c];
        }
        __syncthreads();

        float accs[16][4];
#pragma unroll
        for (int nt = 0; nt < 16; nt++)
#pragma unroll
            for (int e = 0; e < 4; e++) accs[nt][e] = 0.f;
#pragma unroll
        for (int qq = 0; qq < 2; qq++) {
            uint32_t a0 = qf[4 * qq], a1 = qf[4 * qq + 1];
            uint32_t a2 = qf[4 * qq + 2], a3 = qf[4 * qq + 3];
#pragma unroll
            for (int nt = 0; nt < 16; nt++) {
                int n = 8 * nt + g;
                uint32_t b0 = Ks[n * 20 + 8 * qq + tig];
                uint32_t b1 = Ks[n * 20 + 8 * qq + 4 + tig];
                mma_bf16(accs[nt], a0, a1, a2, a3, b0, b1);
            }
        }
        float lm0 = -1e30f, lm1 = -1e30f;
#pragma unroll
        for (int nt = 0; nt < 16; nt++) {
            accs[nt][0] *= CS; accs[nt][1] *= CS;
            accs[nt][2] *= CS; accs[nt][3] *= CS;
            lm0 = fmaxf(lm0, fmaxf(accs[nt][0], accs[nt][1]));
            lm1 = fmaxf(lm1, fmaxf(accs[nt][2], accs[nt][3]));
        }
#pragma unroll
        for (int o = 1; o <= 2; o <<= 1) {
            lm0 = fmaxf(lm0, __shfl_xor_sync(0xffffffffu, lm0, o));
            lm1 = fmaxf(lm1, __shfl_xor_sync(0xffffffffu, lm1, o));
        }
        float mn0 = fmaxf(m0s, lm0), mn1 = fmaxf(m1s, lm1);
        float al0 = fexp2(m0s - mn0), al1 = fexp2(m1s - mn1);
        m0s = mn0; m1s = mn1;

        float ps0 = 0.f, ps1 = 0.f;
        uint32_t Pf[32];
#pragma unroll
        for (int nt = 0; nt < 16; nt++) {
            float p00 = fexp2(accs[nt][0] - mn0);
            float p01 = fexp2(accs[nt][1] - mn0);
            float p10 = fexp2(accs[nt][2] - mn1);
            float p11 = fexp2(accs[nt][3] - mn1);
            ps0 += p00 + p01; ps1 += p10 + p11;
            int q2 = nt >> 1, off = (nt & 1) * 2;
            Pf[4 * q2 + off]     = pack_bf16(p00, p01);
            Pf[4 * q2 + off + 1] = pack_bf16(p10, p11);
        }
        l0p = l0p * al0 + ps0;
        l1p = l1p * al1 + ps1;
#pragma unroll
        for (int nt = 0; nt < 4; nt++) {
            acc_o[nt][0] *= al0; acc_o[nt][1] *= al0;
            acc_o[nt][2] *= al1; acc_o[nt][3] *= al1;
        }
#pragma unroll
        for (int q = 0; q < 8; q++) {
            uint32_t a0 = Pf[4 * q], a1 = Pf[4 * q + 1];
            uint32_t a2 = Pf[4 * q + 2], a3 = Pf[4 * q + 3];
#pragma unroll
            for (int nt = 0; nt < 4; nt++) {
                int n = 8 * nt + g;
                uint32_t b0 = VTs[n * 68 + 8 * q + tig];
                uint32_t b1 = VTs[n * 68 + 8 * q + 4 + tig];
                mma_bf16(acc_o[nt], a0, a1, a2, a3, b0, b1);
            }
        }
    }

#pragma unroll
    for (int o = 1; o <= 2; o <<= 1) {
        l0p += __shfl_xor_sync(0xffffffffu, l0p, o);
        l1p += __shfl_xor_sync(0xffffffffu, l1p, o);
    }
    float inv0 = 1.f / l0p, inv1 = 1.f / l1p;
    uint32_t* oU = (uint32_t*)g_o_bf;
#pragma unroll
    for (int nt = 0; nt < 4; nt++) {
        oU[(q0 + r0i) * 128 + h * 16 + 4 * nt + tig] =
            pack_bf16(acc_o[nt][0] * inv0, acc_o[nt][1] * inv0);
        oU[(q0 + r1i) * 128 + h * 16 + 4 * nt + tig] =
            pack_bf16(acc_o[nt][2] * inv1, acc_o[nt][3] * inv1);
    }
}

// ---------------- persistent fused all-pairs MLP -----------------------------
// 148 blocks x 384 threads. Weights staged ONCE per block; loop over 3072
// work items (i, j-tile-of-192). Per-iteration staging = Ap row into the
// .x lane of resident sPack (no extra SMEM).
#define OFF_W1   0
#define OFF_W2   33792
#define OFF_W3   50688
#define OFF_W4   55040
#define OFF_PACK 56192
#define OFF_LGB  57216
#define OFF_B2   57728
#define OFF_B3   57856
#define OFF_B4   57920
#define OFF_W5   57952
#define OFF_B5   57984
#define SMEM_U32 57988
#define SMEM_BYTES (SMEM_U32 * 4)
#define NWORK    3072
#define NBLOCKS  148

__global__ __launch_bounds__(384, 1) void fused_pairs_reg(
    const float* __restrict__ boxes,
    const float* __restrict__ w1,
    const float* __restrict__ Ap,
    const uint32_t* __restrict__ attbf,
    const uint32_t* __restrict__ bpbf,
    const uint4* __restrict__ w1v, const uint4* __restrict__ w2v,
    const uint4* __restrict__ w3v, const uint4* __restrict__ w4v,
    const float* __restrict__ lng, const float* __restrict__ lnb,
    const float* __restrict__ b2, const float* __restrict__ b3,
    const float* __restrict__ b4,
    const float* __restrict__ w5, const float* __restrict__ b5,
    float* __restrict__ out)
{
    extern __shared__ uint32_t sm[];
    uint32_t* W1s = sm + OFF_W1;
    uint32_t* W2s = sm + OFF_W2;
    uint32_t* W3s = sm + OFF_W3;
    uint32_t* W4s = sm + OFF_W4;
    float4*   sPack = (float4*)(sm + OFF_PACK);
    float2*   sLgb  = (float2*)(sm + OFF_LGB);
    float*    sB2   = (float*)(sm + OFF_B2);
    float*    sB3   = (float*)(sm + OFF_B3);
    float*    sB4   = (float*)(sm + OFF_B4);
    float*    sW5   = (float*)(sm + OFF_W5);
    float*    sB5   = (float*)(sm + OFF_B5);

    const int t  = threadIdx.x;
    const int w  = t >> 5;
    const int lane = t & 31;
    const int g   = lane >> 2;
    const int tig = lane & 3;

    // ---- one-time staging: weights + i-independent consts
    for (int idx = t; idx < 8192; idx += 384) {
        int r = idx >> 5, c4 = idx & 31;
        *(uint4*)&W1s[r * 132 + c4 * 4] = w1v[idx];
    }
    for (int idx = t; idx < 4096; idx += 384) {
        int r = idx >> 5, c4 = idx & 31;
        *(uint4*)&W2s[r * 132 + c4 * 4] = w2v[idx];
    }
    for (int idx = t; idx < 1024; idx += 384) {
        int r = idx >> 4, c4 = idx & 15;
        *(uint4*)&W3s[r * 68 + c4 * 4] = w3v[idx];
    }
    for (int idx = t; idx < 256; idx += 384) {
        int r = idx >> 3, c4 = idx & 7;
        *(uint4*)&W4s[r * 36 + c4 * 4] = w4v[idx];
    }
    if (t < 256) {
        int k = t;
        sPack[k] = make_float4(0.f, w1[k * 771 + 768],
                               w1[k * 771 + 769], w1[k * 771 + 770]);
        sLgb[k]  = make_float2(lng[k], lnb[k]);
        if (k < 128) sB2[k] = b2[k];
        if (k < 64)  sB3[k] = b3[k];
        if (k < 32)  { sB4[k] = b4[k]; sW5[k] = w5[k]; }
        if (k == 0)  sB5[0] = b5[0];
    }

    const int r0 = w * 16 + g, r1 = r0 + 8;

    for (int wk = blockIdx.x; wk < NWORK; wk += NBLOCKS) {
        const int i  = wk >> 2;
        const int j0 = (wk & 3) * 192;
        const int jr0 = j0 + r0, jr1 = j0 + r1;

        __syncthreads();   // prior iteration's sPack readers done
        if (t < 256) sPack[t].x = Ap[i * 256 + t];
        __syncthreads();   // sPack.x visible

        float bxi = boxes[i * 4], byi = boxes[i * 4 + 1];
        float dy0 = byi - boxes[jr0 * 4 + 1];
        float dy1 = byi - boxes[jr1 * 4 + 1];
        float sx0 = fabsf(bxi - boxes[jr0 * 4]), sya0 = fabsf(dy0), sys0 = dy0;
        float sx1 = fabsf(bxi - boxes[jr1 * 4]), sya1 = fabsf(dy1), sys1 = dy1;

        uint32_t A1[64];
#pragma unroll
        for (int q = 0; q < 16; q++) {
            int p0 = 8 * q + tig, p1 = p0 + 4;
            float2 ai0 = unpack_bf16(attbf[i * 128 + p0]);
            float2 ai1 = unpack_bf16(attbf[i * 128 + p1]);
            float2 j00 = unpack_bf16(attbf[jr0 * 128 + p0]);
            float2 j10 = unpack_bf16(attbf[jr1 * 128 + p0]);
            float2 j01 = unpack_bf16(attbf[jr0 * 128 + p1]);
            float2 j11 = unpack_bf16(attbf[jr1 * 128 + p1]);
            A1[4 * q]     = pack_bf16(j00.x * ai0.x, j00.y * ai0.y);
            A1[4 * q + 1] = pack_bf16(j10.x * ai0.x, j10.y * ai0.y);
            A1[4 * q + 2] = pack_bf16(j01.x * ai1.x, j01.y * ai1.y);
            A1[4 * q + 3] = pack_bf16(j11.x * ai1.x, j11.y * ai1.y);
        }

        uint32_t H1[64];
        float sum0 = 0.f, sq0 = 0.f, sum1 = 0.f, sq1 = 0.f;
#pragma unroll
        for (int h = 0; h < 2; h++) {
            float acc[16][4];
#pragma unroll
            for (int ntl = 0; ntl < 16; ntl++)
#pragma unroll
                for (int q = 0; q < 4; q++) acc[ntl][q] = 0.f;

#pragma unroll
            for (int q = 0; q < 16; q++) {
                uint32_t a0 = A1[4 * q],     a1 = A1[4 * q + 1];
                uint32_t a2 = A1[4 * q + 2], a3 = A1[4 * q + 3];
#pragma unroll
                for (int ntl = 0; ntl < 16; ntl++) {
                    int n = (h * 16 + ntl) * 8 + g;
                    uint32_t b0 = W1s[n * 132 + 8 * q + tig];
                    uint32_t b1 = W1s[n * 132 + 8 * q + 4 + tig];
                    mma_bf16(acc[ntl], a0, a1, a2, a3, b0, b1);
                }
            }
#pragma unroll
            for (int ntl = 0; ntl < 16; ntl++) {
                int nt = h * 16 + ntl;
                int c0 = 8 * nt + 2 * tig;
                float4 p0 = sPack[c0], p1 = sPack[c0 + 1];
                float2 bp0 = unpack_bf16(bpbf[jr0 * 128 + 4 * nt + tig]);
                float2 bp1 = unpack_bf16(bpbf[jr1 * 128 + 4 * nt + tig]);
                float v00 = acc[ntl][0] + p0.x + sx0 * p0.y + sya0 * p0.z + sys0 * p0.w + bp0.x;
                float v01 = acc[ntl][1] + p1.x + sx0 * p1.y + sya0 * p1.z + sys0 * p1.w + bp0.y;
                float v10 = acc[ntl][2] + p0.x + sx1 * p0.y + sya1 * p0.z + sys1 * p0.w + bp1.x;
                float v11 = acc[ntl][3] + p1.x + sx1 * p1.y + sya1 * p1.z + sys1 * p1.w + bp1.y;
                v00 = fmaxf(v00, 0.f); v01 = fmaxf(v01, 0.f);
                v10 = fmaxf(v10, 0.f); v11 = fmaxf(v11, 0.f);
                sum0 += v00 + v01; sq0 += v00 * v00 + v01 * v01;
                sum1 += v10 + v11; sq1 += v10 * v10 + v11 * v11;
                int q2 = nt >> 1, off = (nt & 1) * 2;
                H1[4 * q2 + off]     = pack_bf16(v00, v01);
                H1[4 * q2 + off + 1] = pack_bf16(v10, v11);
            }
        }

#pragma unroll
        for (int o = 1; o <= 2; o <<= 1) {
            sum0 += __shfl_xor_sync(0xffffffffu, sum0, o);
            sq0  += __shfl_xor_sync(0xffffffffu, sq0,  o);
            sum1 += __shfl_xor_sync(0xffffffffu, sum1, o);
            sq1  += __shfl_xor_sync(0xffffffffu, sq1,  o);
        }
        float mu0 = sum0 * (1.f / 256.f);
        float rs0 = rsqrtf(sq0 * (1.f / 256.f) - mu0 * mu0 + 1e-5f);
        float mu1 = sum1 * (1.f / 256.f);
        float rs1 = rsqrtf(sq1 * (1.f / 256.f) - mu1 * mu1 + 1e-5f);
#pragma unroll
        for (int q = 0; q < 16; q++) {
#pragma unroll
            for (int e2 = 0; e2 < 2; e2++) {
                int col = 16 * q + 8 * e2 + 2 * tig;
                float2 gb0 = sLgb[col], gb1 = sLgb[col + 1];
#pragma unroll
                for (int e = 0; e < 2; e++) {
                    int idx = 4 * q + 2 * e2 + e;
                    float2 v = unpack_bf16(H1[idx]);
                    float m = e ? mu1 : mu0, rr = e ? rs1 : rs0;
                    H1[idx] = pack_bf16((v.x - m) * rr * gb0.x + gb0.y,
                                        (v.y - m) * rr * gb1.x + gb1.y);
                }
            }
        }

        uint32_t H2[32];
#pragma unroll
        for (int h = 0; h < 2; h++) {
            float acc[8][4];
#pragma unroll
            for (int ntl = 0; ntl < 8; ntl++)
#pragma unroll
                for (int q = 0; q < 4; q++) acc[ntl][q] = 0.f;
#pragma unroll
            for (int q = 0; q < 16; q++) {
                uint32_t a0 = H1[4 * q],     a1 = H1[4 * q + 1];
                uint32_t a2 = H1[4 * q + 2], a3 = H1[4 * q + 3];
#pragma unroll
                for (int ntl = 0; ntl < 8; ntl++) {
                    int n = (h * 8 + ntl) * 8 + g;
                    uint32_t b0 = W2s[n * 132 + 8 * q + tig];
                    uint32_t b1 = W2s[n * 132 + 8 * q + 4 + tig];
                    mma_bf16(acc[ntl], a0, a1, a2, a3, b0, b1);
                }
            }
#pragma unroll
            for (int ntl = 0; ntl < 8; ntl++) {
                int nt = h * 8 + ntl;
                int c0 = 8 * nt + 2 * tig;
                float v00 = fmaxf(acc[ntl][0] + sB2[c0], 0.f);
                float v01 = fmaxf(acc[ntl][1] + sB2[c0 + 1], 0.f);
                float v10 = fmaxf(acc[ntl][2] + sB2[c0], 0.f);
                float v11 = fmaxf(acc[ntl][3] + sB2[c0 + 1], 0.f);
                int q2 = nt >> 1, off = (nt & 1) * 2;
                H2[4 * q2 + off]     = pack_bf16(v00, v01);
                H2[4 * q2 + off + 1] = pack_bf16(v10, v11);
            }
        }

        uint32_t H3[16];
        {
            float acc[8][4];
#pragma unroll
            for (int ntl = 0; ntl < 8; ntl++)
#pragma unroll
                for (int q = 0; q < 4; q++) acc[ntl][q] = 0.f;
#pragma unroll
            for (int q = 0; q < 8; q++) {
                uint32_t a0 = H2[4 * q],     a1 = H2[4 * q + 1];
                uint32_t a2 = H2[4 * q + 2], a3 = H2[4 * q + 3];
#pragma unroll
                for (int ntl = 0; ntl < 8; ntl++) {
                    int n = ntl * 8 + g;
                    uint32_t b0 = W3s[n * 68 + 8 * q + tig];
                    uint32_t b1 = W3s[n * 68 + 8 * q + 4 + tig];
                    mma_bf16(acc[ntl], a0, a1, a2, a3, b0, b1);
                }
            }
#pragma unroll
            for (int nt = 0; nt < 8; nt++) {
                int c0 = 8 * nt + 2 * tig;
                float v00 = fmaxf(acc[nt][0] + sB3[c0], 0.f);
                float v01 = fmaxf(acc[nt][1] + sB3[c0 + 1], 0.f);
                float v10 = fmaxf(acc[nt][2] + sB3[c0], 0.f);
                float v11 = fmaxf(acc[nt][3] + sB3[c0 + 1], 0.f);
                int q2 = nt >> 1, off = (nt & 1) * 2;
                H3[4 * q2 + off]     = pack_bf16(v00, v01);
                H3[4 * q2 + off + 1] = pack_bf16(v10, v11);
            }
        }

        {
            float acc[4][4];
#pragma unroll
            for (int ntl = 0; ntl < 4; ntl++)
#pragma unroll
                for (int q = 0; q < 4; q++) acc[ntl][q] = 0.f;
#pragma unroll
            for (int q = 0; q < 4; q++) {
                uint32_t a0 = H3[4 * q],     a1 = H3[4 * q + 1];
                uint32_t a2 = H3[4 * q + 2], a3 = H3[4 * q + 3];
#pragma unroll
                for (int ntl = 0; ntl < 4; ntl++) {
                    int n = ntl * 8 + g;
                    uint32_t b0 = W4s[n * 36 + 8 * q + tig];
                    uint32_t b1 = W4s[n * 36 + 8 * q + 4 + tig];
                    mma_bf16(acc[ntl], a0, a1, a2, a3, b0, b1);
                }
            }
            float p0 = 0.f, p1 = 0.f;
#pragma unroll
            for (int nt = 0; nt < 4; nt++) {
                int c0 = 8 * nt + 2 * tig;
                p0 += fmaxf(acc[nt][0] + sB4[c0], 0.f) * sW5[c0]
                    + fmaxf(acc[nt][1] + sB4[c0 + 1], 0.f) * sW5[c0 + 1];
                p1 += fmaxf(acc[nt][2] + sB4[c0], 0.f) * sW5[c0]
                    + fmaxf(acc[nt][3] + sB4[c0 + 1], 0.f) * sW5[c0 + 1];
            }
#pragma unroll
            for (int o = 1; o <= 2; o <<= 1) {
                p0 += __shfl_xor_sync(0xffffffffu, p0, o);
                p1 += __shfl_xor_sync(0xffffffffu, p1, o);
            }
            if (tig == 0) {
                float bb = sB5[0];
                out[i * 768 + jr0] = (jr0 == i) ? -1000000000.0f : p0 + bb;
                out[i * 768 + jr1] = (jr1 == i) ? -1000000000.0f : p1 + bb;
            }
        }
    }
}

// ---------------- host launch ------------------------------------------------
extern "C" void kernel_launch(void* const* d_in, const int* in_sizes, int n_in,
                              void* d_out, int out_size)
{
    (void)in_sizes; (void)n_in; (void)out_size;
    const float* features = (const float*)d_in[0];
    const float* boxes    = (const float*)d_in[1];
    const float* in_w     = (const float*)d_in[2];
    const float* in_b     = (const float*)d_in[3];
    const float* out_w    = (const float*)d_in[4];
    const float* out_b    = (const float*)d_in[5];
    const float* w1       = (const float*)d_in[6];
    const float* b1       = (const float*)d_in[7];
    const float* lng      = (const float*)d_in[8];
    const float* lnb      = (const float*)d_in[9];
    const float* w2       = (const float*)d_in[10];
    const float* b2       = (const float*)d_in[11];
    const float* w3       = (const float*)d_in[12];
    const float* b3       = (const float*)d_in[13];
    const float* w4       = (const float*)d_in[14];
    const float* b4       = (const float*)d_in[15];
    const float* w5       = (const float*)d_in[16];
    const float* b5       = (const float*)d_in[17];
    float* out = (float*)d_out;

    void *featbf, *inwbf, *outwbf, *w1abf, *w1bbf, *w1cbf, *w2bf, *w3bf, *w4bf;
    void *qkvbf, *obf, *attbf, *bpbf;
    float* Apb;
    cudaGetSymbolAddress(&featbf, g_feat_bf);
    cudaGetSymbolAddress(&inwbf,  g_inw_bf);
    cudaGetSymbolAddress(&outwbf, g_outw_bf);
    cudaGetSymbolAddress(&w1abf,  g_w1a_bf);
    cudaGetSymbolAddress(&w1bbf,  g_w1b_bf);
    cudaGetSymbolAddress(&w1cbf,  g_w1c_bf);
    cudaGetSymbolAddress(&w2bf,   g_w2_bf);
    cudaGetSymbolAddress(&w3bf,   g_w3_bf);
    cudaGetSymbolAddress(&w4bf,   g_w4_bf);
    cudaGetSymbolAddress(&qkvbf,  g_qkv_bf);
    cudaGetSymbolAddress(&obf,    g_o_bf);
    cudaGetSymbolAddress(&attbf,  g_att_bf);
    cudaGetSymbolAddress(&bpbf,   g_Bp_bf);
    cudaGetSymbolAddress((void**)&Apb, g_Ap);

    cudaFuncSetAttribute(gemm_bf256,
                         cudaFuncAttributeMaxDynamicSharedMemorySize, GEMM_SMEM_BYTES);
    cudaFuncSetAttribute(fused_pairs_reg,
                         cudaFuncAttributeMaxDynamicSharedMemorySize, SMEM_BYTES);

    convert_pre<<<768, 256>>>(features, in_w, out_w, w1, w2, w3, w4);

    gemm_bf256<<<dim3(6, 6), 256, GEMM_SMEM_BYTES>>>(
        (const uint4*)featbf, (const uint4*)inwbf, in_b,
        nullptr, (uint32_t*)qkvbf, 768);

    build_vT<<<256, 256>>>();

    attn_flash<<<dim3(6, 8), 256>>>();

    gemm_bf256<<<dim3(2, 6), 256, GEMM_SMEM_BYTES>>>(
        (const uint4*)obf, (const uint4*)outwbf, out_b,
        nullptr, (uint32_t*)attbf, 256);

    gemm_bf256<<<dim3(2, 6), 256, GEMM_SMEM_BYTES>>>(
        (const uint4*)attbf, (const uint4*)w1abf, b1,
        Apb, nullptr, 256);

    gemm_bf256<<<dim3(2, 6), 256, GEMM_SMEM_BYTES>>>(
        (const uint4*)attbf, (const uint4*)w1bbf, nullptr,
        nullptr, (uint32_t*)bpbf, 256);

    fused_pairs_reg<<<NBLOCKS, 384, SMEM_BYTES>>>(
        boxes, w1, Apb,
        (const uint32_t*)attbf, (const uint32_t*)bpbf,
        (const uint4*)w1cbf, (const uint4*)w2bf,
        (const uint4*)w3bf, (const uint4*)w4bf,
        lng, lnb, b2, b3, b4, w5, b5, out);
}

// round 14
// speedup vs baseline: 1.3754x; 1.0281x over previous
#include <cuda_runtime.h>
#include <cuda_bf16.h>
#include <cstdint>
#include <math.h>

#define NTOK 768
#define DMODEL 256
#define NHEAD 8

// ---------------- scratch (device globals; no allocations allowed) ----------
__device__ __nv_bfloat16 g_feat_bf[NTOK * DMODEL];
__device__ __nv_bfloat16 g_inw_bf[768 * 256];
__device__ __nv_bfloat16 g_outw_bf[256 * 256];
__device__ __nv_bfloat16 g_w1ab_bf[512 * 256];     // rows 0-255 w1a, 256-511 w1b
__device__ __nv_bfloat16 g_w1c_bf[256 * 256];
__device__ __nv_bfloat16 g_w2_bf[128 * 256];
__device__ __nv_bfloat16 g_w3_bf[64 * 128];
__device__ __nv_bfloat16 g_w4_bf[32 * 64];
__device__ __nv_bfloat16 g_qkv_bf[NTOK * 768];
__device__ __nv_bfloat16 g_vT_bf[NHEAD * 32 * NTOK];
__device__ __nv_bfloat16 g_o_bf[NTOK * DMODEL];
__device__ __nv_bfloat16 g_att_bf[NTOK * DMODEL];
__device__ __nv_bfloat16 g_Bp_bf[NTOK * DMODEL];
__device__ float g_Ap[NTOK * DMODEL];
// split-KV attention scratch
__device__ float g_osplit[2 * NTOK * DMODEL];
__device__ float g_msplit[2 * NHEAD * NTOK];
__device__ float g_lsplit[2 * NHEAD * NTOK];

// ---------------- helpers ----------------------------------------------------
__device__ __forceinline__ void mma_bf16(float* c, unsigned a0, unsigned a1,
                                         unsigned a2, unsigned a3,
                                         unsigned b0, unsigned b1)
{
    asm volatile(
        "mma.sync.aligned.m16n8k16.row.col.f32.bf16.bf16.f32 "
        "{%0,%1,%2,%3}, {%4,%5,%6,%7}, {%8,%9}, {%0,%1,%2,%3};"
        : "+f"(c[0]), "+f"(c[1]), "+f"(c[2]), "+f"(c[3])
        : "r"(a0), "r"(a1), "r"(a2), "r"(a3), "r"(b0), "r"(b1));
}
__device__ __forceinline__ unsigned pack_bf16(float a, float b)
{
    __nv_bfloat162 h;
    h.x = __float2bfloat16_rn(a);
    h.y = __float2bfloat16_rn(b);
    return *reinterpret_cast<unsigned*>(&h);
}
__device__ __forceinline__ float2 unpack_bf16(unsigned u)
{
    __nv_bfloat162 h = *reinterpret_cast<__nv_bfloat162*>(&u);
    return make_float2(__bfloat162float(h.x), __bfloat162float(h.y));
}
__device__ __forceinline__ float fexp2(float x)
{
    float y;
    asm("ex2.approx.ftz.f32 %0, %1;" : "=f"(y) : "f"(x));
    return y;
}

// ---------------- conversions -------------------------------------------------
__global__ void convert_pre(const float* __restrict__ features,
                            const float* __restrict__ in_w,
                            const float* __restrict__ out_w,
                            const float* __restrict__ w1,
                            const float* __restrict__ w2,
                            const float* __restrict__ w3,
                            const float* __restrict__ w4)
{
    int t = blockIdx.x * 256 + threadIdx.x;
    if (t < 196608) {
        g_feat_bf[t] = __float2bfloat16_rn(features[t]);
        g_inw_bf[t]  = __float2bfloat16_rn(in_w[t]);
    }
    if (t < 65536) {
        int n = t >> 8, d = t & 255;
        g_outw_bf[t] = __float2bfloat16_rn(out_w[t]);
        g_w1ab_bf[t]         = __float2bfloat16_rn(w1[n * 771 + d]);
        g_w1ab_bf[65536 + t] = __float2bfloat16_rn(w1[n * 771 + 256 + d]);
        g_w1c_bf[t]          = __float2bfloat16_rn(w1[n * 771 + 512 + d]);
    }
    if (t < 32768) g_w2_bf[t] = __float2bfloat16_rn(w2[t]);
    if (t < 8192)  g_w3_bf[t] = __float2bfloat16_rn(w3[t]);
    if (t < 2048)  g_w4_bf[t] = __float2bfloat16_rn(w4[t]);
}

__global__ void build_vT()
{
    int row = blockIdx.x;
    for (int m = threadIdx.x; m < NTOK; m += 256)
        g_vT_bf[row * NTOK + m] = g_qkv_bf[m * 768 + 512 + row];
}

// ---------------- bf16 GEMM, K=256, 128x128 tile, 256 threads ----------------
// mode 0: normal (Cf and/or Cb, pitch from N)
// mode 3: split512 — gn<256 -> Cf fp32 (pitch 256), gn>=256 -> Cb bf16x2 (pitch 128)
#define GEMM_SMEM_U32 33792
#define GEMM_SMEM_BYTES (GEMM_SMEM_U32 * 4)

__global__ __launch_bounds__(256, 1) void gemm_bf256(
    const uint4* __restrict__ A4, const uint4* __restrict__ B4,
    const float* __restrict__ bias,
    float* __restrict__ Cf, uint32_t* __restrict__ Cb, int N, int mode)
{
    extern __shared__ uint32_t sg[];
    uint32_t* As = sg;
    uint32_t* Bs = sg + 16896;

    const int m0 = blockIdx.y * 128;
    const int n0 = blockIdx.x * 128;
    const int t  = threadIdx.x;
    const int w  = t >> 5;
    const int lane = t & 31;
    const int g   = lane >> 2;
    const int tig = lane & 3;
    const int r0i = w * 16 + g, r1i = r0i + 8;

    for (int idx = t; idx < 4096; idx += 256) {
        int r = idx >> 5, c4 = idx & 31;
        *(uint4*)&As[r * 132 + c4 * 4] = A4[(m0 + r) * 32 + c4];
        *(uint4*)&Bs[r * 132 + c4 * 4] = B4[(n0 + r) * 32 + c4];
    }
    __syncthreads();

    float acc[16][4];
#pragma unroll
    for (int nt = 0; nt < 16; nt++)
#pragma unroll
        for (int q = 0; q < 4; q++) acc[nt][q] = 0.f;

#pragma unroll
    for (int q = 0; q < 16; q++) {
        uint32_t a0 = As[r0i * 132 + 8 * q + tig];
        uint32_t a1 = As[r1i * 132 + 8 * q + tig];
        uint32_t a2 = As[r0i * 132 + 8 * q + 4 + tig];
        uint32_t a3 = As[r1i * 132 + 8 * q + 4 + tig];
#pragma unroll
        for (int nt = 0; nt < 16; nt++) {
            int n = 8 * nt + g;
            uint32_t b0 = Bs[n * 132 + 8 * q + tig];
            uint32_t b1 = Bs[n * 132 + 8 * q + 4 + tig];
            mma_bf16(acc[nt], a0, a1, a2, a3, b0, b1);
        }
    }

    const int gm0 = m0 + r0i, gm1 = m0 + r1i;
#pragma unroll
    for (int nt = 0; nt < 16; nt++) {
        int gn = n0 + 8 * nt + 2 * tig;
        float bi0 = bias ? bias[gn] : 0.f;
        float bi1 = bias ? bias[gn + 1] : 0.f;
        float v00 = acc[nt][0] + bi0, v01 = acc[nt][1] + bi1;
        float v10 = acc[nt][2] + bi0, v11 = acc[nt][3] + bi1;
        if (mode == 3) {
            if (gn < 256) {
                *(float2*)&Cf[gm0 * 256 + gn] = make_float2(v00, v01);
                *(float2*)&Cf[gm1 * 256 + gn] = make_float2(v10, v11);
            } else {
                Cb[gm0 * 128 + ((gn - 256) >> 1)] = pack_bf16(v00, v01);
                Cb[gm1 * 128 + ((gn - 256) >> 1)] = pack_bf16(v10, v11);
            }
        } else {
            if (Cf) {
                *(float2*)&Cf[(size_t)gm0 * N + gn] = make_float2(v00, v01);
                *(float2*)&Cf[(size_t)gm1 * N + gn] = make_float2(v10, v11);
            }
            if (Cb) {
                Cb[gm0 * (N >> 1) + (gn >> 1)] = pack_bf16(v00, v01);
                Cb[gm1 * (N >> 1) + (gn >> 1)] = pack_bf16(v10, v11);
            }
        }
    }
}

// ---------------- split-KV flash attention -----------------------------------
// Grid (6 q-tiles, 8 heads, 2 kv-splits), 256 thr. Each split handles 3 of 6
// k-tiles; emits unnormalized partial o (fp32) + per-row (m, l).
__global__ __launch_bounds__(256, 1) void attn_flash()
{
    __shared__ uint32_t Ks[128 * 20];
    __shared__ uint32_t VTs[32 * 68];

    const int q0 = blockIdx.x * 128;
    const int h  = blockIdx.y;
    const int s  = blockIdx.z;
    const int t  = threadIdx.x;
    const int w  = t >> 5;
    const int lane = t & 31;
    const int g   = lane >> 2;
    const int tig = lane & 3;
    const int r0i = w * 16 + g, r1i = r0i + 8;

    const uint32_t* qkvU = (const uint32_t*)g_qkv_bf;
    const uint32_t* vtU  = (const uint32_t*)g_vT_bf;

    const float CS = 1.4426950408889634f * 0.17677669529663687f;

    uint32_t qf[8];
#pragma unroll
    for (int qq = 0; qq < 2; qq++) {
        qf[4 * qq]     = qkvU[(q0 + r0i) * 384 + h * 16 + 8 * qq + tig];
        qf[4 * qq + 1] = qkvU[(q0 + r1i) * 384 + h * 16 + 8 * qq + tig];
        qf[4 * qq + 2] = qkvU[(q0 + r0i) * 384 + h * 16 + 8 * qq + 4 + tig];
        qf[4 * qq + 3] = qkvU[(q0 + r1i) * 384 + h * 16 + 8 * qq + 4 + tig];
    }

    float acc_o[4][4];
#pragma unroll
    for (int nt = 0; nt < 4; nt++)
#pragma unroll
        for (int e = 0; e < 4; e++) acc_o[nt][e] = 0.f;
    float m0s = -1e30f, m1s = -1e30f, l0p = 0.f, l1p = 0.f;

    for (int kk = 0; kk < 3; kk++) {
        const int kt = s * 3 + kk;
        __syncthreads();
        for (int idx = t; idx < 2048; idx += 256) {
            int r = idx >> 4, c = idx & 15;
            Ks[r * 20 + c] = qkvU[(kt * 128 + r) * 384 + 128 + h * 16 + c];
        }
        for (int idx = t; idx < 2048; idx += 256) {
            int d = idx >> 6, c = idx & 63;
            VTs[d * 68 + c] = vtU[(h * 32 + d) * 384 + kt * 64 + c];
        }
        __syncthreads();

        float accs[16][4];
#pragma unroll
        for (int nt = 0; nt < 16; nt++)
#pragma unroll
            for (int e = 0; e < 4; e++) accs[nt][e] = 0.f;
#pragma unroll
        for (int qq = 0; qq < 2; qq++) {
            uint32_t a0 = qf[4 * qq], a1 = qf[4 * qq + 1];
            uint32_t a2 = qf[4 * qq + 2], a3 = qf[4 * qq + 3];
#pragma unroll
            for (int nt = 0; nt < 16; nt++) {
                int n = 8 * nt + g;
                uint32_t b0 = Ks[n * 20 + 8 * qq + tig];
                uint32_t b1 = Ks[n * 20 + 8 * qq + 4 + tig];
                mma_bf16(accs[nt], a0, a1, a2, a3, b0, b1);
            }
        }
        float lm0 = -1e30f, lm1 = -1e30f;
#pragma unroll
        for (int nt = 0; nt < 16; nt++) {
            accs[nt][0] *= CS; accs[nt][1] *= CS;
            accs[nt][2] *= CS; accs[nt][3] *= CS;
            lm0 = fmaxf(lm0, fmaxf(accs[nt][0], accs[nt][1]));
            lm1 = fmaxf(lm1, fmaxf(accs[nt][2], accs[nt][3]));
        }
#pragma unroll
        for (int o = 1; o <= 2; o <<= 1) {
            lm0 = fmaxf(lm0, __shfl_xor_sync(0xffffffffu, lm0, o));
            lm1 = fmaxf(lm1, __shfl_xor_sync(0xffffffffu, lm1, o));
        }
        float mn0 = fmaxf(m0s, lm0), mn1 = fmaxf(m1s, lm1);
        float al0 = fexp2(m0s - mn0), al1 = fexp2(m1s - mn1);
        m0s = mn0; m1s = mn1;

        float ps0 = 0.f, ps1 = 0.f;
        uint32_t Pf[32];
#pragma unroll
        for (int nt = 0; nt < 16; nt++) {
            float p00 = fexp2(accs[nt][0] - mn0);
            float p01 = fexp2(accs[nt][1] - mn0);
            float p10 = fexp2(accs[nt][2] - mn1);
            float p11 = fexp2(accs[nt][3] - mn1);
            ps0 += p00 + p01; ps1 += p10 + p11;
            int q2 = nt >> 1, off = (nt & 1) * 2;
            Pf[4 * q2 + off]     = pack_bf16(p00, p01);
            Pf[4 * q2 + off + 1] = pack_bf16(p10, p11);
        }
        l0p = l0p * al0 + ps0;
        l1p = l1p * al1 + ps1;
#pragma unroll
        for (int nt = 0; nt < 4; nt++) {
            acc_o[nt][0] *= al0; acc_o[nt][1] *= al0;
            acc_o[nt][2] *= al1; acc_o[nt][3] *= al1;
        }
#pragma unroll
        for (int q = 0; q < 8; q++) {
            uint32_t a0 = Pf[4 * q], a1 = Pf[4 * q + 1];
            uint32_t a2 = Pf[4 * q + 2], a3 = Pf[4 * q + 3];
#pragma unroll
            for (int nt = 0; nt < 4; nt++) {
                int n = 8 * nt + g;
                uint32_t b0 = VTs[n * 68 + 8 * q + tig];
                uint32_t b1 = VTs[n * 68 + 8 * q + 4 + tig];
                mma_bf16(acc_o[nt], a0, a1, a2, a3, b0, b1);
            }
        }
    }

    // quad-reduce l; emit partial (o unnormalized, m, l)
#pragma unroll
    for (int o = 1; o <= 2; o <<= 1) {
        l0p += __shfl_xor_sync(0xffffffffu, l0p, o);
        l1p += __shfl_xor_sync(0xffffffffu, l1p, o);
    }
    float* oS = g_osplit + s * NTOK * DMODEL;
#pragma unroll
    for (int nt = 0; nt < 4; nt++) {
        *(float2*)&oS[(q0 + r0i) * 256 + h * 32 + 8 * nt + 2 * tig] =
            make_float2(acc_o[nt][0], acc_o[nt][1]);
        *(float2*)&oS[(q0 + r1i) * 256 + h * 32 + 8 * nt + 2 * tig] =
            make_float2(acc_o[nt][2], acc_o[nt][3]);
    }
    if (tig == 0) {
        g_msplit[s * 6144 + h * 768 + q0 + r0i] = m0s;
        g_lsplit[s * 6144 + h * 768 + q0 + r0i] = l0p;
        g_msplit[s * 6144 + h * 768 + q0 + r1i] = m1s;
        g_lsplit[s * 6144 + h * 768 + q0 + r1i] = l1p;
    }
}

// combine the two kv-splits -> bf16 o
__global__ void attn_combine()
{
    int q = blockIdx.x, t = threadIdx.x;
    int head = t >> 5;
    float m0 = g_msplit[head * 768 + q];
    float m1 = g_msplit[6144 + head * 768 + q];
    float l0 = g_lsplit[head * 768 + q];
    float l1 = g_lsplit[6144 + head * 768 + q];
    float M  = fmaxf(m0, m1);
    float e0 = fexp2(m0 - M), e1 = fexp2(m1 - M);
    float inv = 1.f / (l0 * e0 + l1 * e1);
    float v = (g_osplit[q * 256 + t] * e0 + g_osplit[196608 + q * 256 + t] * e1) * inv;
    g_o_bf[q * 256 + t] = __float2bfloat16_rn(v);
}

// ---------------- persistent fused all-pairs MLP (R13 proven) ----------------
#define OFF_W1   0
#define OFF_W2   33792
#define OFF_W3   50688
#define OFF_W4   55040
#define OFF_PACK 56192
#define OFF_LGB  57216
#define OFF_B2   57728
#define OFF_B3   57856
#define OFF_B4   57920
#define OFF_W5   57952
#define OFF_B5   57984
#define SMEM_U32 57988
#define SMEM_BYTES (SMEM_U32 * 4)
#define NWORK    3072
#define NBLOCKS  148

__global__ __launch_bounds__(384, 1) void fused_pairs_reg(
    const float* __restrict__ boxes,
    const float* __restrict__ w1,
    const float* __restrict__ Ap,
    const uint32_t* __restrict__ attbf,
    const uint32_t* __restrict__ bpbf,
    const uint4* __restrict__ w1v, const uint4* __restrict__ w2v,
    const uint4* __restrict__ w3v, const uint4* __restrict__ w4v,
    const float* __restrict__ lng, const float* __restrict__ lnb,
    const float* __restrict__ b2, const float* __restrict__ b3,
    const float* __restrict__ b4,
    const float* __restrict__ w5, const float* __restrict__ b5,
    float* __restrict__ out)
{
    extern __shared__ uint32_t sm[];
    uint32_t* W1s = sm + OFF_W1;
    uint32_t* W2s = sm + OFF_W2;
    uint32_t* W3s = sm + OFF_W3;
    uint32_t* W4s = sm + OFF_W4;
    float4*   sPack = (float4*)(sm + OFF_PACK);
    float2*   sLgb  = (float2*)(sm + OFF_LGB);
    float*    sB2   = (float*)(sm + OFF_B2);
    float*    sB3   = (float*)(sm + OFF_B3);
    float*    sB4   = (float*)(sm + OFF_B4);
    float*    sW5   = (float*)(sm + OFF_W5);
    float*    sB5   = (float*)(sm + OFF_B5);

    const int t  = threadIdx.x;
    const int w  = t >> 5;
    const int lane = t & 31;
    const int g   = lane >> 2;
    const int tig = lane & 3;

    for (int idx = t; idx < 8192; idx += 384) {
        int r = idx >> 5, c4 = idx & 31;
        *(uint4*)&W1s[r * 132 + c4 * 4] = w1v[idx];
    }
    for (int idx = t; idx < 4096; idx += 384) {
        int r = idx >> 5, c4 = idx & 31;
        *(uint4*)&W2s[r * 132 + c4 * 4] = w2v[idx];
    }
    for (int idx = t; idx < 1024; idx += 384) {
        int r = idx >> 4, c4 = idx & 15;
        *(uint4*)&W3s[r * 68 + c4 * 4] = w3v[idx];
    }
    for (int idx = t; idx < 256; idx += 384) {
        int r = idx >> 3, c4 = idx & 7;
        *(uint4*)&W4s[r * 36 + c4 * 4] = w4v[idx];
    }
    if (t < 256) {
        int k = t;
        sPack[k] = make_float4(0.f, w1[k * 771 + 768],
                               w1[k * 771 + 769], w1[k * 771 + 770]);
        sLgb[k]  = make_float2(lng[k], lnb[k]);
        if (k < 128) sB2[k] = b2[k];
        if (k < 64)  sB3[k] = b3[k];
        if (k < 32)  { sB4[k] = b4[k]; sW5[k] = w5[k]; }
        if (k == 0)  sB5[0] = b5[0];
    }

    const int r0 = w * 16 + g, r1 = r0 + 8;

    for (int wk = blockIdx.x; wk < NWORK; wk += NBLOCKS) {
        const int i  = wk >> 2;
        const int j0 = (wk & 3) * 192;
        const int jr0 = j0 + r0, jr1 = j0 + r1;

        __syncthreads();
        if (t < 256) sPack[t].x = Ap[i * 256 + t];
        __syncthreads();

        float bxi = boxes[i * 4], byi = boxes[i * 4 + 1];
        float dy0 = byi - boxes[jr0 * 4 + 1];
        float dy1 = byi - boxes[jr1 * 4 + 1];
        float sx0 = fabsf(bxi - boxes[jr0 * 4]), sya0 = fabsf(dy0), sys0 = dy0;
        float sx1 = fabsf(bxi - boxes[jr1 * 4]), sya1 = fabsf(dy1), sys1 = dy1;

        uint32_t A1[64];
#pragma unroll
        for (int q = 0; q < 16; q++) {
            int p0 = 8 * q + tig, p1 = p0 + 4;
            float2 ai0 = unpack_bf16(attbf[i * 128 + p0]);
            float2 ai1 = unpack_bf16(attbf[i * 128 + p1]);
            float2 j00 = unpack_bf16(attbf[jr0 * 128 + p0]);
            float2 j10 = unpack_bf16(attbf[jr1 * 128 + p0]);
            float2 j01 = unpack_bf16(attbf[jr0 * 128 + p1]);
            float2 j11 = unpack_bf16(attbf[jr1 * 128 + p1]);
            A1[4 * q]     = pack_bf16(j00.x * ai0.x, j00.y * ai0.y);
            A1[4 * q + 1] = pack_bf16(j10.x * ai0.x, j10.y * ai0.y);
            A1[4 * q + 2] = pack_bf16(j01.x * ai1.x, j01.y * ai1.y);
            A1[4 * q + 3] = pack_bf16(j11.x * ai1.x, j11.y * ai1.y);
        }

        uint32_t H1[64];
        float sum0 = 0.f, sq0 = 0.f, sum1 = 0.f, sq1 = 0.f;
#pragma unroll
        for (int h = 0; h < 2; h++) {
            float acc[16][4];
#pragma unroll
            for (int ntl = 0; ntl < 16; ntl++)
#pragma unroll
                for (int q = 0; q < 4; q++) acc[ntl][q] = 0.f;

#pragma unroll
            for (int q = 0; q < 16; q++) {
                uint32_t a0 = A1[4 * q],     a1 = A1[4 * q + 1];
                uint32_t a2 = A1[4 * q + 2], a3 = A1[4 * q + 3];
#pragma unroll
                for (int ntl = 0; ntl < 16; ntl++) {
                    int n = (h * 16 + ntl) * 8 + g;
                    uint32_t b0 = W1s[n * 132 + 8 * q + tig];
                    uint32_t b1 = W1s[n * 132 + 8 * q + 4 + tig];
                    mma_bf16(acc[ntl], a0, a1, a2, a3, b0, b1);
                }
            }
#pragma unroll
            for (int ntl = 0; ntl < 16; ntl++) {
                int nt = h * 16 + ntl;
                int c0 = 8 * nt + 2 * tig;
                float4 p0 = sPack[c0], p1 = sPack[c0 + 1];
                float2 bp0 = unpack_bf16(bpbf[jr0 * 128 + 4 * nt + tig]);
                float2 bp1 = unpack_bf16(bpbf[jr1 * 128 + 4 * nt + tig]);
                float v00 = acc[ntl][0] + p0.x + sx0 * p0.y + sya0 * p0.z + sys0 * p0.w + bp0.x;
                float v01 = acc[ntl][1] + p1.x + sx0 * p1.y + sya0 * p1.z + sys0 * p1.w + bp0.y;
                float v10 = acc[ntl][2] + p0.x + sx1 * p0.y + sya1 * p0.z + sys1 * p0.w + bp1.x;
                float v11 = acc[ntl][3] + p1.x + sx1 * p1.y + sya1 * p1.z + sys1 * p1.w + bp1.y;
                v00 = fmaxf(v00, 0.f); v01 = fmaxf(v01, 0.f);
                v10 = fmaxf(v10, 0.f); v11 = fmaxf(v11, 0.f);
                sum0 += v00 + v01; sq0 += v00 * v00 + v01 * v01;
                sum1 += v10 + v11; sq1 += v10 * v10 + v11 * v11;
                int q2 = nt >> 1, off = (nt & 1) * 2;
                H1[4 * q2 + off]     = pack_bf16(v00, v01);
                H1[4 * q2 + off + 1] = pack_bf16(v10, v11);
            }
        }

#pragma unroll
        for (int o = 1; o <= 2; o <<= 1) {
            sum0 += __shfl_xor_sync(0xffffffffu, sum0, o);
            sq0  += __shfl_xor_sync(0xffffffffu, sq0,  o);
            sum1 += __shfl_xor_sync(0xffffffffu, sum1, o);
            sq1  += __shfl_xor_sync(0xffffffffu, sq1,  o);
        }
        float mu0 = sum0 * (1.f / 256.f);
        float rs0 = rsqrtf(sq0 * (1.f / 256.f) - mu0 * mu0 + 1e-5f);
        float mu1 = sum1 * (1.f / 256.f);
        float rs1 = rsqrtf(sq1 * (1.f / 256.f) - mu1 * mu1 + 1e-5f);
#pragma unroll
        for (int q = 0; q < 16; q++) {
#pragma unroll
            for (int e2 = 0; e2 < 2; e2++) {
                int col = 16 * q + 8 * e2 + 2 * tig;
                float2 gb0 = sLgb[col], gb1 = sLgb[col + 1];
#pragma unroll
                for (int e = 0; e < 2; e++) {
                    int idx = 4 * q + 2 * e2 + e;
                    float2 v = unpack_bf16(H1[idx]);
                    float m = e ? mu1 : mu0, rr = e ? rs1 : rs0;
                    H1[idx] = pack_bf16((v.x - m) * rr * gb0.x + gb0.y,
                                        (v.y - m) * rr * gb1.x + gb1.y);
                }
            }
        }

        uint32_t H2[32];
#pragma unroll
        for (int h = 0; h < 2; h++) {
            float acc[8][4];
#pragma unroll
            for (int ntl = 0; ntl < 8; ntl++)
#pragma unroll
                for (int q = 0; q < 4; q++) acc[ntl][q] = 0.f;
#pragma unroll
            for (int q = 0; q < 16; q++) {
                uint32_t a0 = H1[4 * q],     a1 = H1[4 * q + 1];
                uint32_t a2 = H1[4 * q + 2], a3 = H1[4 * q + 3];
#pragma unroll
                for (int ntl = 0; ntl < 8; ntl++) {
                    int n = (h * 8 + ntl) * 8 + g;
                    uint32_t b0 = W2s[n * 132 + 8 * q + tig];
                    uint32_t b1 = W2s[n * 132 + 8 * q + 4 + tig];
                    mma_bf16(acc[ntl], a0, a1, a2, a3, b0, b1);
                }
            }
#pragma unroll
            for (int ntl = 0; ntl < 8; ntl++) {
                int nt = h * 8 + ntl;
                int c0 = 8 * nt + 2 * tig;
                float v00 = fmaxf(acc[ntl][0] + sB2[c0], 0.f);
                float v01 = fmaxf(acc[ntl][1] + sB2[c0 + 1], 0.f);
                float v10 = fmaxf(acc[ntl][2] + sB2[c0], 0.f);
                float v11 = fmaxf(acc[ntl][3] + sB2[c0 + 1], 0.f);
                int q2 = nt >> 1, off = (nt & 1) * 2;
                H2[4 * q2 + off]     = pack_bf16(v00, v01);
                H2[4 * q2 + off + 1] = pack_bf16(v10, v11);
            }
        }

        uint32_t H3[16];
        {
            float acc[8][4];
#pragma unroll
            for (int ntl = 0; ntl < 8; ntl++)
#pragma unroll
                for (int q = 0; q < 4; q++) acc[ntl][q] = 0.f;
#pragma unroll
            for (int q = 0; q < 8; q++) {
                uint32_t a0 = H2[4 * q],     a1 = H2[4 * q + 1];
                uint32_t a2 = H2[4 * q + 2], a3 = H2[4 * q + 3];
#pragma unroll
                for (int ntl = 0; ntl < 8; ntl++) {
                    int n = ntl * 8 + g;
                    uint32_t b0 = W3s[n * 68 + 8 * q + tig];
                    uint32_t b1 = W3s[n * 68 + 8 * q + 4 + tig];
                    mma_bf16(acc[ntl], a0, a1, a2, a3, b0, b1);
                }
            }
#pragma unroll
            for (int nt = 0; nt < 8; nt++) {
                int c0 = 8 * nt + 2 * tig;
                float v00 = fmaxf(acc[nt][0] + sB3[c0], 0.f);
                float v01 = fmaxf(acc[nt][1] + sB3[c0 + 1], 0.f);
                float v10 = fmaxf(acc[nt][2] + sB3[c0], 0.f);
                float v11 = fmaxf(acc[nt][3] + sB3[c0 + 1], 0.f);
                int q2 = nt >> 1, off = (nt & 1) * 2;
                H3[4 * q2 + off]     = pack_bf16(v00, v01);
                H3[4 * q2 + off + 1] = pack_bf16(v10, v11);
            }
        }

        {
            float acc[4][4];
#pragma unroll
            for (int ntl = 0; ntl < 4; ntl++)
#pragma unroll
                for (int q = 0; q < 4; q++) acc[ntl][q] = 0.f;
#pragma unroll
            for (int q = 0; q < 4; q++) {
                uint32_t a0 = H3[4 * q],     a1 = H3[4 * q + 1];
                uint32_t a2 = H3[4 * q + 2], a3 = H3[4 * q + 3];
#pragma unroll
                for (int ntl = 0; ntl < 4; ntl++) {
                    int n = ntl * 8 + g;
                    uint32_t b0 = W4s[n * 36 + 8 * q + tig];
                    uint32_t b1 = W4s[n * 36 + 8 * q + 4 + tig];
                    mma_bf16(acc[ntl], a0, a1, a2, a3, b0, b1);
                }
            }
            float p0 = 0.f, p1 = 0.f;
#pragma unroll
            for (int nt = 0; nt < 4; nt++) {
                int c0 = 8 * nt + 2 * tig;
                p0 += fmaxf(acc[nt][0] + sB4[c0], 0.f) * sW5[c0]
                    + fmaxf(acc[nt][1] + sB4[c0 + 1], 0.f) * sW5[c0 + 1];
                p1 += fmaxf(acc[nt][2] + sB4[c0], 0.f) * sW5[c0]
                    + fmaxf(acc[nt][3] + sB4[c0 + 1], 0.f) * sW5[c0 + 1];
            }
#pragma unroll
            for (int o = 1; o <= 2; o <<= 1) {
                p0 += __shfl_xor_sync(0xffffffffu, p0, o);
                p1 += __shfl_xor_sync(0xffffffffu, p1, o);
            }
            if (tig == 0) {
                float bb = sB5[0];
                out[i * 768 + jr0] = (jr0 == i) ? -1000000000.0f : p0 + bb;
                out[i * 768 + jr1] = (jr1 == i) ? -1000000000.0f : p1 + bb;
            }
        }
    }
}

// ---------------- host launch ------------------------------------------------
extern "C" void kernel_launch(void* const* d_in, const int* in_sizes, int n_in,
                              void* d_out, int out_size)
{
    (void)in_sizes; (void)n_in; (void)out_size;
    const float* features = (const float*)d_in[0];
    const float* boxes    = (const float*)d_in[1];
    const float* in_w     = (const float*)d_in[2];
    const float* in_b     = (const float*)d_in[3];
    const float* out_w    = (const float*)d_in[4];
    const float* out_b    = (const float*)d_in[5];
    const float* w1       = (const float*)d_in[6];
    const float* b1       = (const float*)d_in[7];
    const float* lng      = (const float*)d_in[8];
    const float* lnb      = (const float*)d_in[9];
    const float* w2       = (const float*)d_in[10];
    const float* b2       = (const float*)d_in[11];
    const float* w3       = (const float*)d_in[12];
    const float* b3       = (const float*)d_in[13];
    const float* w4       = (const float*)d_in[14];
    const float* b4       = (const float*)d_in[15];
    const float* w5       = (const float*)d_in[16];
    const float* b5       = (const float*)d_in[17];
    float* out = (float*)d_out;

    void *featbf, *inwbf, *outwbf, *w1ab, *w1cbf, *w2bf, *w3bf, *w4bf;
    void *qkvbf, *obf, *attbf, *bpbf;
    float* Apb;
    cudaGetSymbolAddress(&featbf, g_feat_bf);
    cudaGetSymbolAddress(&inwbf,  g_inw_bf);
    cudaGetSymbolAddress(&outwbf, g_outw_bf);
    cudaGetSymbolAddress(&w1ab,   g_w1ab_bf);
    cudaGetSymbolAddress(&w1cbf,  g_w1c_bf);
    cudaGetSymbolAddress(&w2bf,   g_w2_bf);
    cudaGetSymbolAddress(&w3bf,   g_w3_bf);
    cudaGetSymbolAddress(&w4bf,   g_w4_bf);
    cudaGetSymbolAddress(&qkvbf,  g_qkv_bf);
    cudaGetSymbolAddress(&obf,    g_o_bf);
    cudaGetSymbolAddress(&attbf,  g_att_bf);
    cudaGetSymbolAddress(&bpbf,   g_Bp_bf);
    cudaGetSymbolAddress((void**)&Apb, g_Ap);

    cudaFuncSetAttribute(gemm_bf256,
                         cudaFuncAttributeMaxDynamicSharedMemorySize, GEMM_SMEM_BYTES);
    cudaFuncSetAttribute(fused_pairs_reg,
                         cudaFuncAttributeMaxDynamicSharedMemorySize, SMEM_BYTES);

    convert_pre<<<768, 256>>>(features, in_w, out_w, w1, w2, w3, w4);

    // qkv = feat @ in_w^T + in_b
    gemm_bf256<<<dim3(6, 6), 256, GEMM_SMEM_BYTES>>>(
        (const uint4*)featbf, (const uint4*)inwbf, in_b,
        nullptr, (uint32_t*)qkvbf, 768, 0);

    build_vT<<<256, 256>>>();

    // split-KV flash attention + combine
    attn_flash<<<dim3(6, 8, 2), 256>>>();
    attn_combine<<<768, 256>>>();

    // att = o @ out_w^T + out_b
    gemm_bf256<<<dim3(2, 6), 256, GEMM_SMEM_BYTES>>>(
        (const uint4*)obf, (const uint4*)outwbf, out_b,
        nullptr, (uint32_t*)attbf, 256, 0);

    // [Ap | Bp] = att @ [w1a;w1b]^T + [b1|0]   (split epilogue)
    gemm_bf256<<<dim3(4, 6), 256, GEMM_SMEM_BYTES>>>(
        (const uint4*)attbf, (const uint4*)w1ab, b1,
        Apb, (uint32_t*)bpbf, 512, 3);

    fused_pairs_reg<<<NBLOCKS, 384, SMEM_BYTES>>>(
        boxes, w1, Apb,
        (const uint32_t*)attbf, (const uint32_t*)bpbf,
        (const uint4*)w1cbf, (const uint4*)w2bf,
        (const uint4*)w3bf, (const uint4*)w4bf,
        lng, lnb, b2, b3, b4, w5, b5, out);
}